// round 1
// baseline (speedup 1.0000x reference)
#include <cuda_runtime.h>
#include <cstdint>

#define T_STEPS 512
#define B_SZ    1024
#define D_IN    128
#define H_SZ    256
#define G3      (3 * H_SZ)   // 768

#define SC_GRID 128          // persistent scan blocks (<= 148 SMs, 1 block/SM)

// ---------------------------------------------------------------------------
// Scratch (device globals: allocation-free per harness rules)
// ---------------------------------------------------------------------------
__device__ float g_gi[(size_t)T_STEPS * B_SZ * G3];   // 1.61 GB: x @ W_ih^T + b_ih
__device__ float g_h[2][B_SZ * H_SZ];                 // ping-pong hidden state
__device__ unsigned g_bar_count;                      // wraps to 0 every barrier
__device__ volatile unsigned g_bar_phase;             // monotone; consumed as delta

// ---------------------------------------------------------------------------
// Kernel A: gi = x @ W_ih^T + b_ih      (M=T*B=524288, N=768, K=128)
// Block tile 128(M) x 64(N), full K in smem (k-major), 256 threads, micro 8x4.
// ---------------------------------------------------------------------------
__global__ void __launch_bounds__(256)
gi_gemm(const float* __restrict__ x,
        const float* __restrict__ W_ih,
        const float* __restrict__ b_ih)
{
    extern __shared__ float sm[];
    float* As = sm;               // [k][m] : 128*128 floats (64 KB)
    float* Bs = sm + 128 * 128;   // [k][n] : 128*64  floats (32 KB)

    const int tid = threadIdx.x;
    const size_t mbase = (size_t)blockIdx.y * 128;
    const int nbase = blockIdx.x * 64;

    // Fill As (transposed): lanes carry distinct m -> conflict-free STS
    {
        const int ml = tid & 127;
        const int half = tid >> 7;
        const float* xp = x + (mbase + ml) * D_IN;
#pragma unroll
        for (int f = 0; f < 16; f++) {
            int kc = half * 64 + f * 4;
            float4 v = *reinterpret_cast<const float4*>(xp + kc);
            As[(kc + 0) * 128 + ml] = v.x;
            As[(kc + 1) * 128 + ml] = v.y;
            As[(kc + 2) * 128 + ml] = v.z;
            As[(kc + 3) * 128 + ml] = v.w;
        }
        const int nl = tid & 63;
        const int q  = tid >> 6;
        const float* wp = W_ih + (size_t)(nbase + nl) * D_IN;
#pragma unroll
        for (int f = 0; f < 8; f++) {
            int kc = q * 32 + f * 4;
            float4 v = *reinterpret_cast<const float4*>(wp + kc);
            Bs[(kc + 0) * 64 + nl] = v.x;
            Bs[(kc + 1) * 64 + nl] = v.y;
            Bs[(kc + 2) * 64 + nl] = v.z;
            Bs[(kc + 3) * 64 + nl] = v.w;
        }
    }
    __syncthreads();

    const int tx = tid & 15;   // N
    const int ty = tid >> 4;   // M
    float acc[8][4] = {};

#pragma unroll 8
    for (int k = 0; k < 128; k++) {
        float4 a0 = *reinterpret_cast<const float4*>(&As[k * 128 + ty * 8]);
        float4 a1 = *reinterpret_cast<const float4*>(&As[k * 128 + ty * 8 + 4]);
        float4 bv = *reinterpret_cast<const float4*>(&Bs[k * 64 + tx * 4]);
        float am[8] = {a0.x, a0.y, a0.z, a0.w, a1.x, a1.y, a1.z, a1.w};
#pragma unroll
        for (int i = 0; i < 8; i++) {
            acc[i][0] += am[i] * bv.x;
            acc[i][1] += am[i] * bv.y;
            acc[i][2] += am[i] * bv.z;
            acc[i][3] += am[i] * bv.w;
        }
    }

    float4 bias = *reinterpret_cast<const float4*>(b_ih + nbase + tx * 4);
#pragma unroll
    for (int i = 0; i < 8; i++) {
        float4 r;
        r.x = acc[i][0] + bias.x;
        r.y = acc[i][1] + bias.y;
        r.z = acc[i][2] + bias.z;
        r.w = acc[i][3] + bias.w;
        *reinterpret_cast<float4*>(g_gi + (mbase + ty * 8 + i) * G3 + nbase + tx * 4) = r;
    }
}

// ---------------------------------------------------------------------------
// Persistent GRU scan. Grid = 128 blocks (16 b-tiles x 8 j-tiles), 256 threads.
// Block owns b in [b0,b0+64), hidden cols j in [j0,j0+32) for all 3 gates.
// W_hh slice (96x256) lives in smem for the whole kernel.
// ---------------------------------------------------------------------------
__device__ __forceinline__ void grid_barrier(unsigned target)
{
    __syncthreads();
    __threadfence();                 // every thread publishes its writes
    __syncthreads();
    if (threadIdx.x == 0) {
        unsigned old = atomicInc(&g_bar_count, SC_GRID - 1);   // self-resetting
        if (old == SC_GRID - 1) {
            g_bar_phase = target;    // release
        } else {
            while (g_bar_phase != target) { }                  // spin (L2 polls)
        }
    }
    __syncthreads();
}

__global__ void __launch_bounds__(256, 1)
gru_scan(const float* __restrict__ h0,
         const float* __restrict__ masks,
         const float* __restrict__ W_hh,
         const float* __restrict__ b_hh,
         float* __restrict__ out)
{
    extern __shared__ float smem[];
    float* Ws = smem;                 // [96][257]  (stride 257: conflict-free)
    float* hs = smem + 96 * 257;      // [64][260]  (stride 260: f4-aligned, cf)

    const int tid = threadIdx.x;
    const int bi = blockIdx.x >> 3;   // 0..15
    const int ji = blockIdx.x & 7;    // 0..7
    const int b0 = bi * 64;
    const int j0 = ji * 32;

    const unsigned bar_base = g_bar_phase;   // all blocks read before any flip

    // Load this block's W_hh slice once (rows: [r j-slice][z j-slice][n j-slice])
    for (int idx = tid; idx < 96 * 256; idx += 256) {
        int row = idx >> 8;
        int k   = idx & 255;
        int g   = row >> 5;
        int jl  = row & 31;
        Ws[row * 257 + k] = W_hh[((size_t)(g * H_SZ + j0 + jl)) * H_SZ + k];
    }

    const int tx = tid & 15;   // j-thread: jA = tx, jB = tx+16
    const int ty = tid >> 4;   // b-thread: rows ty*4 .. ty*4+3

    float bh[2][3];
#pragma unroll
    for (int g = 0; g < 3; g++) {
        bh[0][g] = b_hh[g * H_SZ + j0 + tx];
        bh[1][g] = b_hh[g * H_SZ + j0 + tx + 16];
    }

    const int hoff0 = (ty * 4 + 0) * 260;
    const int hoff1 = (ty * 4 + 1) * 260;
    const int hoff2 = (ty * 4 + 2) * 260;
    const int hoff3 = (ty * 4 + 3) * 260;
    const int wr_a = (0 * 32 + tx) * 257, wr_b = (0 * 32 + tx + 16) * 257;
    const int wz_a = (1 * 32 + tx) * 257, wz_b = (1 * 32 + tx + 16) * 257;
    const int wn_a = (2 * 32 + tx) * 257, wn_b = (2 * 32 + tx + 16) * 257;

    for (int t = 0; t < T_STEPS; t++) {
        const float* hsrc = (t == 0) ? (h0 + (size_t)b0 * H_SZ)
                                     : (&g_h[t & 1][0] + (size_t)b0 * H_SZ);
        const float* mrow = masks + (size_t)t * B_SZ + b0;

        // Stage masked h tile (64 x 256) into smem; __ldcg dodges stale L1.
#pragma unroll
        for (int it = 0; it < 16; it++) {
            int f4 = it * 256 + tid;
            int r  = f4 >> 6;
            int kc = (f4 & 63) * 4;
            float4 v = __ldcg(reinterpret_cast<const float4*>(hsrc + r * H_SZ + kc));
            float m = __ldg(mrow + r);
            v.x *= m; v.y *= m; v.z *= m; v.w *= m;
            *reinterpret_cast<float4*>(&hs[r * 260 + kc]) = v;
        }
        __syncthreads();

        // GEMM: gh[b, {r,z,n} x j] over K=256.  24 FFMA : 10 LDS per k.
        float acr[4][2] = {}, acz[4][2] = {}, acn[4][2] = {};
#pragma unroll 4
        for (int k = 0; k < H_SZ; k++) {
            float a0 = hs[hoff0 + k];
            float a1 = hs[hoff1 + k];
            float a2 = hs[hoff2 + k];
            float a3 = hs[hoff3 + k];
            float r0 = Ws[wr_a + k], r1 = Ws[wr_b + k];
            float z0 = Ws[wz_a + k], z1 = Ws[wz_b + k];
            float n0 = Ws[wn_a + k], n1 = Ws[wn_b + k];
            acr[0][0] += a0 * r0; acr[0][1] += a0 * r1;
            acr[1][0] += a1 * r0; acr[1][1] += a1 * r1;
            acr[2][0] += a2 * r0; acr[2][1] += a2 * r1;
            acr[3][0] += a3 * r0; acr[3][1] += a3 * r1;
            acz[0][0] += a0 * z0; acz[0][1] += a0 * z1;
            acz[1][0] += a1 * z0; acz[1][1] += a1 * z1;
            acz[2][0] += a2 * z0; acz[2][1] += a2 * z1;
            acz[3][0] += a3 * z0; acz[3][1] += a3 * z1;
            acn[0][0] += a0 * n0; acn[0][1] += a0 * n1;
            acn[1][0] += a1 * n0; acn[1][1] += a1 * n1;
            acn[2][0] += a2 * n0; acn[2][1] += a2 * n1;
            acn[3][0] += a3 * n0; acn[3][1] += a3 * n1;
        }

        // Gates + state update + outputs
        float* hnext = &g_h[(t + 1) & 1][0];
        float* yrow  = out + (size_t)t * B_SZ * H_SZ;
        const int hofs[4] = {hoff0, hoff1, hoff2, hoff3};
#pragma unroll
        for (int i = 0; i < 4; i++) {
            const int b = b0 + ty * 4 + i;
            const float* gib = g_gi + ((size_t)t * B_SZ + b) * G3;
#pragma unroll
            for (int jj = 0; jj < 2; jj++) {
                const int jg = j0 + tx + jj * 16;
                float ir  = __ldcs(gib + jg);
                float iz  = __ldcs(gib + H_SZ + jg);
                float in_ = __ldcs(gib + 2 * H_SZ + jg);
                float hr = ((jj == 0) ? acr[i][0] : acr[i][1]) + bh[jj][0];
                float hz = ((jj == 0) ? acz[i][0] : acz[i][1]) + bh[jj][1];
                float hn = ((jj == 0) ? acn[i][0] : acn[i][1]) + bh[jj][2];
                float r = 1.0f / (1.0f + __expf(-(ir + hr)));
                float z = 1.0f / (1.0f + __expf(-(iz + hz)));
                float n = tanhf(in_ + r * hn);
                float hp = hs[hofs[i] + jg];           // masked h (same j index)
                float hv = (1.0f - z) * n + z * hp;
                hnext[(size_t)b * H_SZ + jg] = hv;
                yrow [(size_t)b * H_SZ + jg] = hv;     // pre-LN y
                if (t == T_STEPS - 1)
                    out[(size_t)T_STEPS * B_SZ * H_SZ + (size_t)b * H_SZ + jg] = hv;
            }
        }

        grid_barrier(bar_base + (unsigned)t + 1u);
    }
}

// ---------------------------------------------------------------------------
// In-place LayerNorm over last dim (256) of y. One warp per (t,b) row.
// ---------------------------------------------------------------------------
__global__ void __launch_bounds__(256)
ln_kernel(float* __restrict__ y,
          const float* __restrict__ lw,
          const float* __restrict__ lb)
{
    const int lane = threadIdx.x & 31;
    const int warp = threadIdx.x >> 5;
    const size_t row = (size_t)blockIdx.x * 8 + warp;
    float* p = y + row * H_SZ;

    float4 v0 = *reinterpret_cast<const float4*>(p + lane * 4);
    float4 v1 = *reinterpret_cast<const float4*>(p + 128 + lane * 4);

    float s = v0.x + v0.y + v0.z + v0.w + v1.x + v1.y + v1.z + v1.w;
#pragma unroll
    for (int o = 16; o; o >>= 1) s += __shfl_xor_sync(0xffffffffu, s, o);
    const float mu = s * (1.0f / 256.0f);

    float q = (v0.x - mu) * (v0.x - mu) + (v0.y - mu) * (v0.y - mu)
            + (v0.z - mu) * (v0.z - mu) + (v0.w - mu) * (v0.w - mu)
            + (v1.x - mu) * (v1.x - mu) + (v1.y - mu) * (v1.y - mu)
            + (v1.z - mu) * (v1.z - mu) + (v1.w - mu) * (v1.w - mu);
#pragma unroll
    for (int o = 16; o; o >>= 1) q += __shfl_xor_sync(0xffffffffu, q, o);
    const float rs = rsqrtf(q * (1.0f / 256.0f) + 1e-5f);

    float4 w0 = *reinterpret_cast<const float4*>(lw + lane * 4);
    float4 w1 = *reinterpret_cast<const float4*>(lw + 128 + lane * 4);
    float4 c0 = *reinterpret_cast<const float4*>(lb + lane * 4);
    float4 c1 = *reinterpret_cast<const float4*>(lb + 128 + lane * 4);

    v0.x = (v0.x - mu) * rs * w0.x + c0.x;
    v0.y = (v0.y - mu) * rs * w0.y + c0.y;
    v0.z = (v0.z - mu) * rs * w0.z + c0.z;
    v0.w = (v0.w - mu) * rs * w0.w + c0.w;
    v1.x = (v1.x - mu) * rs * w1.x + c1.x;
    v1.y = (v1.y - mu) * rs * w1.y + c1.y;
    v1.z = (v1.z - mu) * rs * w1.z + c1.z;
    v1.w = (v1.w - mu) * rs * w1.w + c1.w;

    *reinterpret_cast<float4*>(p + lane * 4) = v0;
    *reinterpret_cast<float4*>(p + 128 + lane * 4) = v1;
}

// ---------------------------------------------------------------------------
extern "C" void kernel_launch(void* const* d_in, const int* in_sizes, int n_in,
                              void* d_out, int out_size)
{
    const float* x     = (const float*)d_in[0];
    const float* h0    = (const float*)d_in[1];   // rnn_states (1,B,H)
    const float* masks = (const float*)d_in[2];   // (T,B,1)
    const float* W_ih  = (const float*)d_in[3];
    const float* W_hh  = (const float*)d_in[4];
    const float* b_ih  = (const float*)d_in[5];
    const float* b_hh  = (const float*)d_in[6];
    const float* ln_w  = (const float*)d_in[7];
    const float* ln_b  = (const float*)d_in[8];
    float* out = (float*)d_out;

    (void)in_sizes; (void)n_in; (void)out_size;

    const int smemA = 128 * 128 * 4 + 128 * 64 * 4;          // 96 KB
    const int smemS = (96 * 257 + 64 * 260) * 4;             // 165,248 B
    cudaFuncSetAttribute(gi_gemm,  cudaFuncAttributeMaxDynamicSharedMemorySize, smemA);
    cudaFuncSetAttribute(gru_scan, cudaFuncAttributeMaxDynamicSharedMemorySize, smemS);

    dim3 gA(G3 / 64, (T_STEPS * B_SZ) / 128);                // (12, 4096)
    gi_gemm<<<gA, 256, smemA>>>(x, W_ih, b_ih);

    gru_scan<<<SC_GRID, 256, smemS>>>(h0, masks, W_hh, b_hh, out);

    ln_kernel<<<(T_STEPS * B_SZ) / 8, 256>>>(out, ln_w, ln_b);
}

// round 2
// speedup vs baseline: 1.0439x; 1.0439x over previous
#include <cuda_runtime.h>
#include <cstdint>

#define T_STEPS 512
#define B_SZ    1024
#define D_IN    128
#define H_SZ    256
#define G3      (3 * H_SZ)   // 768

#define SC_GRID 128          // persistent scan blocks (<= 148 SMs, 1 block/SM)
#define WS_STR  260          // float4-aligned, conflict-light
#define HS_STR  260

// ---------------------------------------------------------------------------
// Scratch (device globals: allocation-free per harness rules)
// ---------------------------------------------------------------------------
__device__ float g_gi[(size_t)T_STEPS * B_SZ * G3];   // 1.61 GB: x @ W_ih^T + b_ih
__device__ unsigned g_bar_count;                      // wraps to 0 every barrier
__device__ volatile unsigned g_bar_phase;             // monotone; consumed as delta

// ---------------------------------------------------------------------------
// Kernel A: gi = x @ W_ih^T + b_ih      (M=T*B=524288, N=768, K=128)
// Block tile 128(M) x 64(N); K processed in 2 chunks of 64 so smem = 48 KB
// -> 2 CTAs/SM (16 warps) for latency hiding. 256 threads, micro 8x4.
// ---------------------------------------------------------------------------
__global__ void __launch_bounds__(256, 2)
gi_gemm(const float* __restrict__ x,
        const float* __restrict__ W_ih,
        const float* __restrict__ b_ih)
{
    extern __shared__ float sm[];
    float* As = sm;              // [k][m] : 64*128 floats (32 KB)
    float* Bs = sm + 64 * 128;   // [k][n] : 64*64  floats (16 KB)

    const int tid = threadIdx.x;
    const size_t mbase = (size_t)blockIdx.y * 128;
    const int nbase = blockIdx.x * 64;

    const int tx = tid & 15;   // N
    const int ty = tid >> 4;   // M
    float acc[8][4] = {};

#pragma unroll
    for (int c = 0; c < 2; c++) {
        const int k0 = c * 64;

        // As (transposed): 2 threads per m-row, 8 float4 each
        {
            const int ml = tid & 127;
            const int half = tid >> 7;
            const float* xp = x + (mbase + ml) * D_IN + k0 + half * 32;
#pragma unroll
            for (int f = 0; f < 8; f++) {
                int kc = half * 32 + f * 4;
                float4 v = *reinterpret_cast<const float4*>(xp + f * 4);
                As[(kc + 0) * 128 + ml] = v.x;
                As[(kc + 1) * 128 + ml] = v.y;
                As[(kc + 2) * 128 + ml] = v.z;
                As[(kc + 3) * 128 + ml] = v.w;
            }
            // Bs: 4 threads per n-row, 4 float4 each
            const int nl = tid & 63;
            const int q  = tid >> 6;
            const float* wp = W_ih + (size_t)(nbase + nl) * D_IN + k0 + q * 16;
#pragma unroll
            for (int f = 0; f < 4; f++) {
                int kc = q * 16 + f * 4;
                float4 v = *reinterpret_cast<const float4*>(wp + f * 4);
                Bs[(kc + 0) * 64 + nl] = v.x;
                Bs[(kc + 1) * 64 + nl] = v.y;
                Bs[(kc + 2) * 64 + nl] = v.z;
                Bs[(kc + 3) * 64 + nl] = v.w;
            }
        }
        __syncthreads();

#pragma unroll 8
        for (int k = 0; k < 64; k++) {
            float4 a0 = *reinterpret_cast<const float4*>(&As[k * 128 + ty * 8]);
            float4 a1 = *reinterpret_cast<const float4*>(&As[k * 128 + ty * 8 + 4]);
            float4 bv = *reinterpret_cast<const float4*>(&Bs[k * 64 + tx * 4]);
            float am[8] = {a0.x, a0.y, a0.z, a0.w, a1.x, a1.y, a1.z, a1.w};
#pragma unroll
            for (int i = 0; i < 8; i++) {
                acc[i][0] += am[i] * bv.x;
                acc[i][1] += am[i] * bv.y;
                acc[i][2] += am[i] * bv.z;
                acc[i][3] += am[i] * bv.w;
            }
        }
        __syncthreads();
    }

    float4 bias = *reinterpret_cast<const float4*>(b_ih + nbase + tx * 4);
#pragma unroll
    for (int i = 0; i < 8; i++) {
        float4 r;
        r.x = acc[i][0] + bias.x;
        r.y = acc[i][1] + bias.y;
        r.z = acc[i][2] + bias.z;
        r.w = acc[i][3] + bias.w;
        *reinterpret_cast<float4*>(g_gi + (mbase + ty * 8 + i) * G3 + nbase + tx * 4) = r;
    }
}

// ---------------------------------------------------------------------------
// Persistent GRU scan. Grid = 128 blocks (16 b-tiles x 8 j-tiles), 256 threads.
// Block owns b in [b0,b0+64), hidden cols j in [j0,j0+32) for all 3 gates.
// W_hh slice (96x256) lives in smem for the whole kernel.
// Previous h is read from the y rows already written to `out` (no ping-pong).
// ---------------------------------------------------------------------------
__device__ __forceinline__ void grid_barrier(unsigned target)
{
    __syncthreads();
    __threadfence();
    __syncthreads();
    if (threadIdx.x == 0) {
        unsigned old = atomicInc(&g_bar_count, SC_GRID - 1);   // self-resetting
        if (old == SC_GRID - 1) {
            g_bar_phase = target;    // release
        } else {
            while (g_bar_phase != target) { }
        }
    }
    __syncthreads();
}

__global__ void __launch_bounds__(256, 1)
gru_scan(const float* __restrict__ h0,
         const float* __restrict__ masks,
         const float* __restrict__ W_hh,
         const float* __restrict__ b_hh,
         float* __restrict__ out)
{
    extern __shared__ float smem[];
    float* Ws = smem;                    // [96][WS_STR]
    float* hs = smem + 96 * WS_STR;      // [64][HS_STR]

    const int tid = threadIdx.x;
    const int bi = blockIdx.x >> 3;   // 0..15
    const int ji = blockIdx.x & 7;    // 0..7
    const int b0 = bi * 64;
    const int j0 = ji * 32;

    const unsigned bar_base = g_bar_phase;   // all blocks read before any flip

    // Load this block's W_hh slice once (rows: [r j-slice][z j-slice][n j-slice])
    for (int idx = tid; idx < 96 * 64; idx += 256) {    // float4 granularity
        int row = idx >> 6;
        int c4  = idx & 63;
        int g   = row >> 5;
        int jl  = row & 31;
        float4 v = *reinterpret_cast<const float4*>(
            W_hh + ((size_t)(g * H_SZ + j0 + jl)) * H_SZ + c4 * 4);
        *reinterpret_cast<float4*>(&Ws[row * WS_STR + c4 * 4]) = v;
    }

    const int tx = tid & 15;   // j-thread: jA = tx, jB = tx+16
    const int ty = tid >> 4;   // b-thread: rows ty*4 .. ty*4+3

    float bh[2][3];
#pragma unroll
    for (int g = 0; g < 3; g++) {
        bh[0][g] = b_hh[g * H_SZ + j0 + tx];
        bh[1][g] = b_hh[g * H_SZ + j0 + tx + 16];
    }

    const int hoff[4] = {(ty * 4 + 0) * HS_STR, (ty * 4 + 1) * HS_STR,
                         (ty * 4 + 2) * HS_STR, (ty * 4 + 3) * HS_STR};
    const int wr_a = (0 * 32 + tx) * WS_STR, wr_b = (0 * 32 + tx + 16) * WS_STR;
    const int wz_a = (1 * 32 + tx) * WS_STR, wz_b = (1 * 32 + tx + 16) * WS_STR;
    const int wn_a = (2 * 32 + tx) * WS_STR, wn_b = (2 * 32 + tx + 16) * WS_STR;

    for (int t = 0; t < T_STEPS; t++) {
        const float* hsrc = (t == 0)
            ? (h0 + (size_t)b0 * H_SZ)
            : (out + ((size_t)(t - 1) * B_SZ + b0) * H_SZ);
        const float* mrow = masks + (size_t)t * B_SZ + b0;

        // Stage masked h tile (64 x 256) into smem; __ldcg dodges stale L1.
#pragma unroll
        for (int it = 0; it < 16; it++) {
            int f4 = it * 256 + tid;
            int r  = f4 >> 6;
            int kc = (f4 & 63) * 4;
            float4 v = __ldcg(reinterpret_cast<const float4*>(hsrc + r * H_SZ + kc));
            float m = __ldg(mrow + r);
            v.x *= m; v.y *= m; v.z *= m; v.w *= m;
            *reinterpret_cast<float4*>(&hs[r * HS_STR + kc]) = v;
        }
        __syncthreads();

        // GEMM over K=256, k chunked by 4 via LDS.128: 10 LDS.128 : 96 FFMA.
        float acr[4][2] = {}, acz[4][2] = {}, acn[4][2] = {};
#pragma unroll 2
        for (int kc = 0; kc < H_SZ; kc += 4) {
            float4 a[4];
            a[0] = *reinterpret_cast<const float4*>(&hs[hoff[0] + kc]);
            a[1] = *reinterpret_cast<const float4*>(&hs[hoff[1] + kc]);
            a[2] = *reinterpret_cast<const float4*>(&hs[hoff[2] + kc]);
            a[3] = *reinterpret_cast<const float4*>(&hs[hoff[3] + kc]);
            float4 r0 = *reinterpret_cast<const float4*>(&Ws[wr_a + kc]);
            float4 r1 = *reinterpret_cast<const float4*>(&Ws[wr_b + kc]);
            float4 z0 = *reinterpret_cast<const float4*>(&Ws[wz_a + kc]);
            float4 z1 = *reinterpret_cast<const float4*>(&Ws[wz_b + kc]);
            float4 n0 = *reinterpret_cast<const float4*>(&Ws[wn_a + kc]);
            float4 n1 = *reinterpret_cast<const float4*>(&Ws[wn_b + kc]);
#pragma unroll
            for (int i = 0; i < 4; i++) {
                acr[i][0] += a[i].x * r0.x + a[i].y * r0.y + a[i].z * r0.z + a[i].w * r0.w;
                acr[i][1] += a[i].x * r1.x + a[i].y * r1.y + a[i].z * r1.z + a[i].w * r1.w;
                acz[i][0] += a[i].x * z0.x + a[i].y * z0.y + a[i].z * z0.z + a[i].w * z0.w;
                acz[i][1] += a[i].x * z1.x + a[i].y * z1.y + a[i].z * z1.z + a[i].w * z1.w;
                acn[i][0] += a[i].x * n0.x + a[i].y * n0.y + a[i].z * n0.z + a[i].w * n0.w;
                acn[i][1] += a[i].x * n1.x + a[i].y * n1.y + a[i].z * n1.z + a[i].w * n1.w;
            }
        }

        // Gates + state update + outputs
        float* yrow = out + (size_t)t * B_SZ * H_SZ;
#pragma unroll
        for (int i = 0; i < 4; i++) {
            const int b = b0 + ty * 4 + i;
            const float* gib = g_gi + ((size_t)t * B_SZ + b) * G3;
#pragma unroll
            for (int jj = 0; jj < 2; jj++) {
                const int jg = j0 + tx + jj * 16;
                float ir  = __ldcs(gib + jg);
                float iz  = __ldcs(gib + H_SZ + jg);
                float in_ = __ldcs(gib + 2 * H_SZ + jg);
                float hr = ((jj == 0) ? acr[i][0] : acr[i][1]) + bh[jj][0];
                float hz = ((jj == 0) ? acz[i][0] : acz[i][1]) + bh[jj][1];
                float hn = ((jj == 0) ? acn[i][0] : acn[i][1]) + bh[jj][2];
                float r = 1.0f / (1.0f + __expf(-(ir + hr)));
                float z = 1.0f / (1.0f + __expf(-(iz + hz)));
                float n = tanhf(in_ + r * hn);
                float hp = hs[hoff[i] + jg];           // masked h (same j index)
                float hv = (1.0f - z) * n + z * hp;
                yrow[(size_t)b * H_SZ + jg] = hv;      // pre-LN y == next h
                if (t == T_STEPS - 1)
                    out[(size_t)T_STEPS * B_SZ * H_SZ + (size_t)b * H_SZ + jg] = hv;
            }
        }

        grid_barrier(bar_base + (unsigned)t + 1u);
    }
}

// ---------------------------------------------------------------------------
// In-place LayerNorm over last dim (256) of y. One warp per (t,b) row.
// ---------------------------------------------------------------------------
__global__ void __launch_bounds__(256)
ln_kernel(float* __restrict__ y,
          const float* __restrict__ lw,
          const float* __restrict__ lb)
{
    const int lane = threadIdx.x & 31;
    const int warp = threadIdx.x >> 5;
    const size_t row = (size_t)blockIdx.x * 8 + warp;
    float* p = y + row * H_SZ;

    float4 v0 = *reinterpret_cast<const float4*>(p + lane * 4);
    float4 v1 = *reinterpret_cast<const float4*>(p + 128 + lane * 4);

    float s = v0.x + v0.y + v0.z + v0.w + v1.x + v1.y + v1.z + v1.w;
#pragma unroll
    for (int o = 16; o; o >>= 1) s += __shfl_xor_sync(0xffffffffu, s, o);
    const float mu = s * (1.0f / 256.0f);

    float q = (v0.x - mu) * (v0.x - mu) + (v0.y - mu) * (v0.y - mu)
            + (v0.z - mu) * (v0.z - mu) + (v0.w - mu) * (v0.w - mu)
            + (v1.x - mu) * (v1.x - mu) + (v1.y - mu) * (v1.y - mu)
            + (v1.z - mu) * (v1.z - mu) + (v1.w - mu) * (v1.w - mu);
#pragma unroll
    for (int o = 16; o; o >>= 1) q += __shfl_xor_sync(0xffffffffu, q, o);
    const float rs = rsqrtf(q * (1.0f / 256.0f) + 1e-5f);

    float4 w0 = *reinterpret_cast<const float4*>(lw + lane * 4);
    float4 w1 = *reinterpret_cast<const float4*>(lw + 128 + lane * 4);
    float4 c0 = *reinterpret_cast<const float4*>(lb + lane * 4);
    float4 c1 = *reinterpret_cast<const float4*>(lb + 128 + lane * 4);

    v0.x = (v0.x - mu) * rs * w0.x + c0.x;
    v0.y = (v0.y - mu) * rs * w0.y + c0.y;
    v0.z = (v0.z - mu) * rs * w0.z + c0.z;
    v0.w = (v0.w - mu) * rs * w0.w + c0.w;
    v1.x = (v1.x - mu) * rs * w1.x + c1.x;
    v1.y = (v1.y - mu) * rs * w1.y + c1.y;
    v1.z = (v1.z - mu) * rs * w1.z + c1.z;
    v1.w = (v1.w - mu) * rs * w1.w + c1.w;

    *reinterpret_cast<float4*>(p + lane * 4) = v0;
    *reinterpret_cast<float4*>(p + 128 + lane * 4) = v1;
}

// ---------------------------------------------------------------------------
extern "C" void kernel_launch(void* const* d_in, const int* in_sizes, int n_in,
                              void* d_out, int out_size)
{
    const float* x     = (const float*)d_in[0];
    const float* h0    = (const float*)d_in[1];   // rnn_states (1,B,H)
    const float* masks = (const float*)d_in[2];   // (T,B,1)
    const float* W_ih  = (const float*)d_in[3];
    const float* W_hh  = (const float*)d_in[4];
    const float* b_ih  = (const float*)d_in[5];
    const float* b_hh  = (const float*)d_in[6];
    const float* ln_w  = (const float*)d_in[7];
    const float* ln_b  = (const float*)d_in[8];
    float* out = (float*)d_out;

    (void)in_sizes; (void)n_in; (void)out_size;

    const int smemA = (64 * 128 + 64 * 64) * 4;              // 48 KB -> 2 CTA/SM
    const int smemS = (96 * WS_STR + 64 * HS_STR) * 4;       // 166,400 B
    cudaFuncSetAttribute(gi_gemm,  cudaFuncAttributeMaxDynamicSharedMemorySize, smemA);
    cudaFuncSetAttribute(gru_scan, cudaFuncAttributeMaxDynamicSharedMemorySize, smemS);

    dim3 gA(G3 / 64, (T_STEPS * B_SZ) / 128);                // (12, 4096)
    gi_gemm<<<gA, 256, smemA>>>(x, W_ih, b_ih);

    gru_scan<<<SC_GRID, 256, smemS>>>(h0, masks, W_hh, b_hh, out);

    ln_kernel<<<(T_STEPS * B_SZ) / 8, 256>>>(out, ln_w, ln_b);
}

// round 4
// speedup vs baseline: 1.9831x; 1.8998x over previous
#include <cuda_runtime.h>
#include <cuda_bf16.h>
#include <cstdint>

#define T_STEPS 512
#define B_SZ    1024
#define D_IN    128
#define H_SZ    256
#define G3      (3 * H_SZ)   // 768

#define SC_GRID 128          // 16 b-tiles x 8 j-tiles, 1 CTA/SM

// ---------------------------------------------------------------------------
// Scratch (device globals)
// ---------------------------------------------------------------------------
__device__ float g_gi[(size_t)T_STEPS * B_SZ * G3];
__device__ __align__(16) unsigned g_hhi[2][B_SZ * H_SZ / 2];  // bf16x2 hi, ping-pong
__device__ __align__(16) unsigned g_hlo[2][B_SZ * H_SZ / 2];  // bf16x2 lo
__device__ unsigned g_bar_count;
__device__ volatile unsigned g_bar_phase;

// ---------------------------------------------------------------------------
// Helpers
// ---------------------------------------------------------------------------
__device__ __forceinline__ unsigned smem_u32(const void* p) {
    unsigned a;
    asm("{ .reg .u64 t; cvta.to.shared.u64 t, %1; cvt.u32.u64 %0, t; }" : "=r"(a) : "l"(p));
    return a;
}

// Tile element layout: row-major [row][256 bf16] = 512 B/row, with 16B-chunk
// XOR swizzle inside each row:  byte_off = row*512 + ((chunk ^ (row&7))<<4)
__device__ __forceinline__ unsigned toff(int row, int chunk) {
    return (unsigned)row * 512u + (unsigned)((chunk ^ (row & 7)) << 4);
}

__device__ __forceinline__ uint4 pack8(const unsigned s[8]) {
    return make_uint4(s[0] | (s[1] << 16), s[2] | (s[3] << 16),
                      s[4] | (s[5] << 16), s[6] | (s[7] << 16));
}

__device__ __forceinline__ void split8(const float v[8], uint4& hi, uint4& lo) {
    unsigned h[8], l[8];
#pragma unroll
    for (int i = 0; i < 8; i++) {
        __nv_bfloat16 bh = __float2bfloat16(v[i]);
        float fh = __bfloat162float(bh);
        __nv_bfloat16 bl = __float2bfloat16(v[i] - fh);
        h[i] = (unsigned)__bfloat16_as_ushort(bh);
        l[i] = (unsigned)__bfloat16_as_ushort(bl);
    }
    hi = pack8(h); lo = pack8(l);
}

__device__ __forceinline__ void unpack2(unsigned hi, unsigned lo, float& f0, float& f1) {
    f0 = __uint_as_float(hi << 16)         + __uint_as_float(lo << 16);
    f1 = __uint_as_float(hi & 0xffff0000u) + __uint_as_float(lo & 0xffff0000u);
}

__device__ __forceinline__ float fast_sigmoid(float x) {
    return __fdividef(1.0f, 1.0f + __expf(-x));
}
__device__ __forceinline__ float fast_tanh(float x) {
    return 1.0f - 2.0f * __fdividef(1.0f, __expf(2.0f * x) + 1.0f);
}

#define LDM4(r, a)                                                             \
    asm volatile("ldmatrix.sync.aligned.m8n8.x4.shared.b16 {%0,%1,%2,%3}, [%4];" \
        : "=r"((r)[0]), "=r"((r)[1]), "=r"((r)[2]), "=r"((r)[3]) : "r"(a))

#define MMA16816(c, a, b0v, b1v)                                               \
    asm volatile("mma.sync.aligned.m16n8k16.row.col.f32.bf16.bf16.f32 "        \
        "{%0,%1,%2,%3}, {%4,%5,%6,%7}, {%8,%9}, {%0,%1,%2,%3};"                \
        : "+f"((c)[0]), "+f"((c)[1]), "+f"((c)[2]), "+f"((c)[3])               \
        : "r"((a)[0]), "r"((a)[1]), "r"((a)[2]), "r"((a)[3]), "r"(b0v), "r"(b1v))

// ---------------------------------------------------------------------------
// Kernel A: gi = x @ W_ih^T + b_ih   (unchanged, known-good fp32 SIMT)
// ---------------------------------------------------------------------------
__global__ void __launch_bounds__(256, 2)
gi_gemm(const float* __restrict__ x,
        const float* __restrict__ W_ih,
        const float* __restrict__ b_ih)
{
    extern __shared__ float sm[];
    float* As = sm;
    float* Bs = sm + 64 * 128;

    const int tid = threadIdx.x;
    const size_t mbase = (size_t)blockIdx.y * 128;
    const int nbase = blockIdx.x * 64;

    const int tx = tid & 15;
    const int ty = tid >> 4;
    float acc[8][4] = {};

#pragma unroll
    for (int c = 0; c < 2; c++) {
        const int k0 = c * 64;
        {
            const int ml = tid & 127;
            const int half = tid >> 7;
            const float* xp = x + (mbase + ml) * D_IN + k0 + half * 32;
#pragma unroll
            for (int f = 0; f < 8; f++) {
                int kc = half * 32 + f * 4;
                float4 v = *reinterpret_cast<const float4*>(xp + f * 4);
                As[(kc + 0) * 128 + ml] = v.x;
                As[(kc + 1) * 128 + ml] = v.y;
                As[(kc + 2) * 128 + ml] = v.z;
                As[(kc + 3) * 128 + ml] = v.w;
            }
            const int nl = tid & 63;
            const int q  = tid >> 6;
            const float* wp = W_ih + (size_t)(nbase + nl) * D_IN + k0 + q * 16;
#pragma unroll
            for (int f = 0; f < 4; f++) {
                int kc = q * 16 + f * 4;
                float4 v = *reinterpret_cast<const float4*>(wp + f * 4);
                Bs[(kc + 0) * 64 + nl] = v.x;
                Bs[(kc + 1) * 64 + nl] = v.y;
                Bs[(kc + 2) * 64 + nl] = v.z;
                Bs[(kc + 3) * 64 + nl] = v.w;
            }
        }
        __syncthreads();

#pragma unroll 8
        for (int k = 0; k < 64; k++) {
            float4 a0 = *reinterpret_cast<const float4*>(&As[k * 128 + ty * 8]);
            float4 a1 = *reinterpret_cast<const float4*>(&As[k * 128 + ty * 8 + 4]);
            float4 bv = *reinterpret_cast<const float4*>(&Bs[k * 64 + tx * 4]);
            float am[8] = {a0.x, a0.y, a0.z, a0.w, a1.x, a1.y, a1.z, a1.w};
#pragma unroll
            for (int i = 0; i < 8; i++) {
                acc[i][0] += am[i] * bv.x;
                acc[i][1] += am[i] * bv.y;
                acc[i][2] += am[i] * bv.z;
                acc[i][3] += am[i] * bv.w;
            }
        }
        __syncthreads();
    }

    float4 bias = *reinterpret_cast<const float4*>(b_ih + nbase + tx * 4);
#pragma unroll
    for (int i = 0; i < 8; i++) {
        float4 r;
        r.x = acc[i][0] + bias.x;
        r.y = acc[i][1] + bias.y;
        r.z = acc[i][2] + bias.z;
        r.w = acc[i][3] + bias.w;
        *reinterpret_cast<float4*>(g_gi + (mbase + ty * 8 + i) * G3 + nbase + tx * 4) = r;
    }
}

// ---------------------------------------------------------------------------
// Grid barrier
// ---------------------------------------------------------------------------
__device__ __forceinline__ void grid_barrier(unsigned target)
{
    __syncthreads();
    __threadfence();
    __syncthreads();
    if (threadIdx.x == 0) {
        unsigned old = atomicInc(&g_bar_count, SC_GRID - 1);
        if (old == SC_GRID - 1) {
            g_bar_phase = target;
        } else {
            while (g_bar_phase != target) { }
        }
    }
    __syncthreads();
}

// ---------------------------------------------------------------------------
// Persistent GRU scan via mma.sync bf16 (3-term split, fp32 accum).
// 128 CTAs = 16 b-tiles(64) x 8 j-tiles(32).   gh[64 x 96] = A[64x256] B^T
// ---------------------------------------------------------------------------
// smem layout (bytes)
#define S_BIAS 0u
#define S_GH   512u           // 64 x 104 fp32 = 26624 B
#define S_AHI  28672u         // 64 x 256 bf16 = 32768 B
#define S_ALO  61440u
#define S_WHI  94208u         // 96 x 256 bf16 = 49152 B
#define S_WLO  143360u
#define SMEM_SCAN 192512
#define GH_STR 104

__global__ void __launch_bounds__(256, 1)
gru_scan_mma(const float* __restrict__ h0,
             const float* __restrict__ masks,
             const float* __restrict__ W_hh,
             const float* __restrict__ b_hh,
             float* __restrict__ out)
{
    extern __shared__ char smem[];
    const unsigned sbase = smem_u32(smem);
    float* sbias = reinterpret_cast<float*>(smem + S_BIAS);
    float* sgh   = reinterpret_cast<float*>(smem + S_GH);

    const int tid = threadIdx.x;
    const int bi = blockIdx.x >> 3;   // 0..15
    const int ji = blockIdx.x & 7;    // 0..7
    const int b0 = bi * 64;
    const int j0 = ji * 32;

    const unsigned bar_base = g_bar_phase;

    // ---- stage W_hh slice (96 rows = [r|z|n] x 32 local j) split to bf16 ----
    for (int c = tid; c < 96 * 32; c += 256) {
        int r  = c >> 5;
        int ch = c & 31;
        int grow = (r >> 5) * H_SZ + j0 + (r & 31);
        float v[8];
        *reinterpret_cast<float4*>(v)     = *reinterpret_cast<const float4*>(W_hh + (size_t)grow * H_SZ + ch * 8);
        *reinterpret_cast<float4*>(v + 4) = *reinterpret_cast<const float4*>(W_hh + (size_t)grow * H_SZ + ch * 8 + 4);
        uint4 hi, lo;
        split8(v, hi, lo);
        unsigned off = toff(r, ch);
        *reinterpret_cast<uint4*>(smem + S_WHI + off) = hi;
        *reinterpret_cast<uint4*>(smem + S_WLO + off) = lo;
    }
    if (tid < 96) sbias[tid] = b_hh[(tid >> 5) * H_SZ + j0 + (tid & 31)];

    // ---- per-thread mma lane mapping ----
    const int lane = tid & 31;
    const int w = tid >> 5;
    const int wm = w & 3;            // m-slice: rows wm*16..+15
    const int wn = w >> 2;           // n-half: cols wn*48..+47
    const int rowA = wm * 16 + (lane & 7) + ((lane & 8) ? 8 : 0);
    const int parA = (lane >> 4) & 1;
    const int rbrel = (lane & 7) + (((lane >> 4) & 1) ? 8 : 0);
    const int parB = (lane >> 3) & 1;
    int rowB[3];
#pragma unroll
    for (int p = 0; p < 3; p++) rowB[p] = wn * 48 + p * 16 + rbrel;

    // ---- gate-phase mapping ----
    const int gr = tid >> 2;         // b row 0..63
    const int gq = tid & 3;
    const int jj0 = gq * 8;          // local j base (8 wide)
    const int b = b0 + gr;
    const int jg = j0 + jj0;

    __syncthreads();

    for (int t = 0; t < T_STEPS; t++) {
        const float* mrow = masks + (size_t)t * B_SZ + b0;

        // ---- stage masked split-h A tile (64 x 256) ----
        if (t == 0) {
#pragma unroll
            for (int c = tid; c < 64 * 32; c += 256) {
                int r = c >> 5, ch = c & 31;
                float m = __ldg(mrow + r);
                const float* hp = h0 + (size_t)(b0 + r) * H_SZ + ch * 8;
                float v[8];
                *reinterpret_cast<float4*>(v)     = *reinterpret_cast<const float4*>(hp);
                *reinterpret_cast<float4*>(v + 4) = *reinterpret_cast<const float4*>(hp + 4);
#pragma unroll
                for (int i = 0; i < 8; i++) v[i] *= m;
                uint4 hi, lo;
                split8(v, hi, lo);
                unsigned off = toff(r, ch);
                *reinterpret_cast<uint4*>(smem + S_AHI + off) = hi;
                *reinterpret_cast<uint4*>(smem + S_ALO + off) = lo;
            }
        } else {
            const int pb = (t - 1) & 1;
#pragma unroll
            for (int c = tid; c < 64 * 32; c += 256) {
                int r = c >> 5, ch = c & 31;
                float m = __ldg(mrow + r);
                size_t gidx = ((size_t)(b0 + r) * H_SZ + ch * 8) >> 3;
                uint4 hi = __ldcg(reinterpret_cast<const uint4*>(g_hhi[pb]) + gidx);
                uint4 lo = __ldcg(reinterpret_cast<const uint4*>(g_hlo[pb]) + gidx);
                if (m == 0.0f) { hi = make_uint4(0,0,0,0); lo = make_uint4(0,0,0,0); }
                unsigned off = toff(r, ch);
                *reinterpret_cast<uint4*>(smem + S_AHI + off) = hi;
                *reinterpret_cast<uint4*>(smem + S_ALO + off) = lo;
            }
        }
        __syncthreads();

        // ---- prefetch gi (hides under mma) ----
        float gir[8], giz[8], gin[8];
        {
            const float* gib = g_gi + ((size_t)t * B_SZ + b) * G3 + jg;
            *reinterpret_cast<float4*>(gir)     = __ldcs(reinterpret_cast<const float4*>(gib));
            *reinterpret_cast<float4*>(gir + 4) = __ldcs(reinterpret_cast<const float4*>(gib + 4));
            *reinterpret_cast<float4*>(giz)     = __ldcs(reinterpret_cast<const float4*>(gib + H_SZ));
            *reinterpret_cast<float4*>(giz + 4) = __ldcs(reinterpret_cast<const float4*>(gib + H_SZ + 4));
            *reinterpret_cast<float4*>(gin)     = __ldcs(reinterpret_cast<const float4*>(gib + 2 * H_SZ));
            *reinterpret_cast<float4*>(gin + 4) = __ldcs(reinterpret_cast<const float4*>(gib + 2 * H_SZ + 4));
        }

        // ---- tensor-core GEMM: 16 k-steps x 3 tile-pairs x 6 mma ----
        float acc[6][4] = {};
#pragma unroll 4
        for (int ks = 0; ks < 16; ks++) {
            const int kc = ks * 2;
            unsigned ahi[4], alo[4];
            unsigned aoffs = (unsigned)rowA * 512u + (unsigned)(((kc + parA) ^ (rowA & 7)) << 4);
            LDM4(ahi, sbase + S_AHI + aoffs);
            LDM4(alo, sbase + S_ALO + aoffs);
#pragma unroll
            for (int p = 0; p < 3; p++) {
                unsigned boffs = (unsigned)rowB[p] * 512u + (unsigned)(((kc + parB) ^ (rowB[p] & 7)) << 4);
                unsigned bh[4], bl[4];
                LDM4(bh, sbase + S_WHI + boffs);
                LDM4(bl, sbase + S_WLO + boffs);
                MMA16816(acc[2 * p],     ahi, bh[0], bh[1]);
                MMA16816(acc[2 * p + 1], ahi, bh[2], bh[3]);
                MMA16816(acc[2 * p],     ahi, bl[0], bl[1]);
                MMA16816(acc[2 * p + 1], ahi, bl[2], bl[3]);
                MMA16816(acc[2 * p],     alo, bh[0], bh[1]);
                MMA16816(acc[2 * p + 1], alo, bh[2], bh[3]);
            }
        }

        // ---- accumulators -> smem gh ----
        {
            const int r0 = wm * 16 + lane / 4;
            const int cb = wn * 48 + (lane % 4) * 2;
#pragma unroll
            for (int i = 0; i < 6; i++) {
                const int col = cb + (i >> 1) * 16 + (i & 1) * 8;
                *reinterpret_cast<float2*>(&sgh[r0 * GH_STR + col])       = make_float2(acc[i][0], acc[i][1]);
                *reinterpret_cast<float2*>(&sgh[(r0 + 8) * GH_STR + col]) = make_float2(acc[i][2], acc[i][3]);
            }
        }
        __syncthreads();

        // ---- gates: thread handles (row gr, 8 j) ----
        {
            float ghr[8], ghz[8], ghn[8], hpv[8], hv[8];
            *reinterpret_cast<float4*>(ghr)     = *reinterpret_cast<const float4*>(&sgh[gr * GH_STR + jj0]);
            *reinterpret_cast<float4*>(ghr + 4) = *reinterpret_cast<const float4*>(&sgh[gr * GH_STR + jj0 + 4]);
            *reinterpret_cast<float4*>(ghz)     = *reinterpret_cast<const float4*>(&sgh[gr * GH_STR + 32 + jj0]);
            *reinterpret_cast<float4*>(ghz + 4) = *reinterpret_cast<const float4*>(&sgh[gr * GH_STR + 32 + jj0 + 4]);
            *reinterpret_cast<float4*>(ghn)     = *reinterpret_cast<const float4*>(&sgh[gr * GH_STR + 64 + jj0]);
            *reinterpret_cast<float4*>(ghn + 4) = *reinterpret_cast<const float4*>(&sgh[gr * GH_STR + 64 + jj0 + 4]);

            // hp from staged split-A (hidden col jg = k index in A tile)
            {
                unsigned off = toff(gr, jg >> 3);
                uint4 hi = *reinterpret_cast<const uint4*>(smem + S_AHI + off);
                uint4 lo = *reinterpret_cast<const uint4*>(smem + S_ALO + off);
                unsigned hu[4] = {hi.x, hi.y, hi.z, hi.w};
                unsigned lu[4] = {lo.x, lo.y, lo.z, lo.w};
#pragma unroll
                for (int q = 0; q < 4; q++) unpack2(hu[q], lu[q], hpv[2 * q], hpv[2 * q + 1]);
            }

#pragma unroll
            for (int i = 0; i < 8; i++) {
                float br = sbias[jj0 + i];
                float bz = sbias[32 + jj0 + i];
                float bn = sbias[64 + jj0 + i];
                float r = fast_sigmoid(gir[i] + ghr[i] + br);
                float z = fast_sigmoid(giz[i] + ghz[i] + bz);
                float n = fast_tanh(gin[i] + r * (ghn[i] + bn));
                hv[i] = (1.0f - z) * n + z * hpv[i];
            }

            float* yp = out + ((size_t)t * B_SZ + b) * H_SZ + jg;
            *reinterpret_cast<float4*>(yp)     = make_float4(hv[0], hv[1], hv[2], hv[3]);
            *reinterpret_cast<float4*>(yp + 4) = make_float4(hv[4], hv[5], hv[6], hv[7]);

            uint4 oh, ol;
            split8(hv, oh, ol);
            const int cb2 = t & 1;
            size_t gidx = ((size_t)b * H_SZ + jg) >> 3;
            reinterpret_cast<uint4*>(g_hhi[cb2])[gidx] = oh;
            reinterpret_cast<uint4*>(g_hlo[cb2])[gidx] = ol;

            if (t == T_STEPS - 1) {
                float* fp = out + (size_t)T_STEPS * B_SZ * H_SZ + (size_t)b * H_SZ + jg;
                *reinterpret_cast<float4*>(fp)     = make_float4(hv[0], hv[1], hv[2], hv[3]);
                *reinterpret_cast<float4*>(fp + 4) = make_float4(hv[4], hv[5], hv[6], hv[7]);
            }
        }

        grid_barrier(bar_base + (unsigned)t + 1u);
    }
}

// ---------------------------------------------------------------------------
// In-place LayerNorm over last dim (256). One warp per (t,b) row.
// ---------------------------------------------------------------------------
__global__ void __launch_bounds__(256)
ln_kernel(float* __restrict__ y,
          const float* __restrict__ lw,
          const float* __restrict__ lb)
{
    const int lane = threadIdx.x & 31;
    const int warp = threadIdx.x >> 5;
    const size_t row = (size_t)blockIdx.x * 8 + warp;
    float* p = y + row * H_SZ;

    float4 v0 = *reinterpret_cast<const float4*>(p + lane * 4);
    float4 v1 = *reinterpret_cast<const float4*>(p + 128 + lane * 4);

    float s = v0.x + v0.y + v0.z + v0.w + v1.x + v1.y + v1.z + v1.w;
#pragma unroll
    for (int o = 16; o; o >>= 1) s += __shfl_xor_sync(0xffffffffu, s, o);
    const float mu = s * (1.0f / 256.0f);

    float q = (v0.x - mu) * (v0.x - mu) + (v0.y - mu) * (v0.y - mu)
            + (v0.z - mu) * (v0.z - mu) + (v0.w - mu) * (v0.w - mu)
            + (v1.x - mu) * (v1.x - mu) + (v1.y - mu) * (v1.y - mu)
            + (v1.z - mu) * (v1.z - mu) + (v1.w - mu) * (v1.w - mu);
#pragma unroll
    for (int o = 16; o; o >>= 1) q += __shfl_xor_sync(0xffffffffu, q, o);
    const float rs = rsqrtf(q * (1.0f / 256.0f) + 1e-5f);

    float4 w0 = *reinterpret_cast<const float4*>(lw + lane * 4);
    float4 w1 = *reinterpret_cast<const float4*>(lw + 128 + lane * 4);
    float4 c0 = *reinterpret_cast<const float4*>(lb + lane * 4);
    float4 c1 = *reinterpret_cast<const float4*>(lb + 128 + lane * 4);

    v0.x = (v0.x - mu) * rs * w0.x + c0.x;
    v0.y = (v0.y - mu) * rs * w0.y + c0.y;
    v0.z = (v0.z - mu) * rs * w0.z + c0.z;
    v0.w = (v0.w - mu) * rs * w0.w + c0.w;
    v1.x = (v1.x - mu) * rs * w1.x + c1.x;
    v1.y = (v1.y - mu) * rs * w1.y + c1.y;
    v1.z = (v1.z - mu) * rs * w1.z + c1.z;
    v1.w = (v1.w - mu) * rs * w1.w + c1.w;

    *reinterpret_cast<float4*>(p + lane * 4) = v0;
    *reinterpret_cast<float4*>(p + 128 + lane * 4) = v1;
}

// ---------------------------------------------------------------------------
extern "C" void kernel_launch(void* const* d_in, const int* in_sizes, int n_in,
                              void* d_out, int out_size)
{
    const float* x     = (const float*)d_in[0];
    const float* h0    = (const float*)d_in[1];
    const float* masks = (const float*)d_in[2];
    const float* W_ih  = (const float*)d_in[3];
    const float* W_hh  = (const float*)d_in[4];
    const float* b_ih  = (const float*)d_in[5];
    const float* b_hh  = (const float*)d_in[6];
    const float* ln_w  = (const float*)d_in[7];
    const float* ln_b  = (const float*)d_in[8];
    float* out = (float*)d_out;

    (void)in_sizes; (void)n_in; (void)out_size;

    const int smemA = (64 * 128 + 64 * 64) * 4;   // 48 KB
    cudaFuncSetAttribute(gi_gemm, cudaFuncAttributeMaxDynamicSharedMemorySize, smemA);
    cudaFuncSetAttribute(gru_scan_mma, cudaFuncAttributeMaxDynamicSharedMemorySize, SMEM_SCAN);

    dim3 gA(G3 / 64, (T_STEPS * B_SZ) / 128);
    gi_gemm<<<gA, 256, smemA>>>(x, W_ih, b_ih);

    gru_scan_mma<<<SC_GRID, 256, SMEM_SCAN>>>(h0, masks, W_hh, b_hh, out);

    ln_kernel<<<(T_STEPS * B_SZ) / 8, 256>>>(out, ln_w, ln_b);
}

// round 5
// speedup vs baseline: 2.6569x; 1.3397x over previous
#include <cuda_runtime.h>
#include <cuda_bf16.h>
#include <cstdint>

#define T_STEPS 512
#define B_SZ    1024
#define D_IN    128
#define H_SZ    256
#define G3      (3 * H_SZ)   // 768

#define SC_GRID 128          // 16 b-tiles x 8 j-tiles, 1 CTA/SM

// ---------------------------------------------------------------------------
// Scratch (device globals)
// ---------------------------------------------------------------------------
__device__ float g_gi[(size_t)T_STEPS * B_SZ * G3];
__device__ __align__(16) unsigned g_hhi[2][B_SZ * H_SZ / 2];  // bf16x2 hi, ping-pong
__device__ __align__(16) unsigned g_hlo[2][B_SZ * H_SZ / 2];  // bf16x2 lo
__device__ unsigned g_bar_count;
__device__ volatile unsigned g_bar_phase;

// ---------------------------------------------------------------------------
// Helpers
// ---------------------------------------------------------------------------
__device__ __forceinline__ unsigned smem_u32(const void* p) {
    unsigned a;
    asm("{ .reg .u64 t; cvta.to.shared.u64 t, %1; cvt.u32.u64 %0, t; }" : "=r"(a) : "l"(p));
    return a;
}

// 256-k rows (512 B/row), 16B-chunk XOR swizzle (scan tiles)
__device__ __forceinline__ unsigned toff(int row, int chunk) {
    return (unsigned)row * 512u + (unsigned)((chunk ^ (row & 7)) << 4);
}
// 128-k rows (256 B/row) variant (gi tiles)
__device__ __forceinline__ unsigned toff128(int row, int chunk) {
    return (unsigned)row * 256u + (unsigned)((chunk ^ (row & 7)) << 4);
}

__device__ __forceinline__ uint4 pack8(const unsigned s[8]) {
    return make_uint4(s[0] | (s[1] << 16), s[2] | (s[3] << 16),
                      s[4] | (s[5] << 16), s[6] | (s[7] << 16));
}

__device__ __forceinline__ void split8(const float v[8], uint4& hi, uint4& lo) {
    unsigned h[8], l[8];
#pragma unroll
    for (int i = 0; i < 8; i++) {
        __nv_bfloat16 bh = __float2bfloat16(v[i]);
        float fh = __bfloat162float(bh);
        __nv_bfloat16 bl = __float2bfloat16(v[i] - fh);
        h[i] = (unsigned)__bfloat16_as_ushort(bh);
        l[i] = (unsigned)__bfloat16_as_ushort(bl);
    }
    hi = pack8(h); lo = pack8(l);
}

__device__ __forceinline__ void unpack2(unsigned hi, unsigned lo, float& f0, float& f1) {
    f0 = __uint_as_float(hi << 16)         + __uint_as_float(lo << 16);
    f1 = __uint_as_float(hi & 0xffff0000u) + __uint_as_float(lo & 0xffff0000u);
}

__device__ __forceinline__ float fast_sigmoid(float x) {
    return __fdividef(1.0f, 1.0f + __expf(-x));
}
__device__ __forceinline__ float fast_tanh(float x) {
    return 1.0f - 2.0f * __fdividef(1.0f, __expf(2.0f * x) + 1.0f);
}

#define LDM4(r, a)                                                             \
    asm volatile("ldmatrix.sync.aligned.m8n8.x4.shared.b16 {%0,%1,%2,%3}, [%4];" \
        : "=r"((r)[0]), "=r"((r)[1]), "=r"((r)[2]), "=r"((r)[3]) : "r"(a))

#define MMA16816(c, a, b0v, b1v)                                               \
    asm volatile("mma.sync.aligned.m16n8k16.row.col.f32.bf16.bf16.f32 "        \
        "{%0,%1,%2,%3}, {%4,%5,%6,%7}, {%8,%9}, {%0,%1,%2,%3};"                \
        : "+f"((c)[0]), "+f"((c)[1]), "+f"((c)[2]), "+f"((c)[3])               \
        : "r"((a)[0]), "r"((a)[1]), "r"((a)[2]), "r"((a)[3]), "r"(b0v), "r"(b1v))

// ---------------------------------------------------------------------------
// Kernel A: gi = x @ W_ih^T + b_ih  via bf16-split mma.sync
// Block 128(M) x 64(N), K=128 fully staged. 256 thr = 8 warps (4M x 2N),
// warp tile 32x32. smem 96 KB -> 2 CTA/SM.
// ---------------------------------------------------------------------------
#define GI_SAHI 0u
#define GI_SALO 32768u
#define GI_SBHI 65536u
#define GI_SBLO 81920u
#define GI_SMEM 98304

__global__ void __launch_bounds__(256, 2)
gi_mma(const float* __restrict__ x,
       const float* __restrict__ W_ih,
       const float* __restrict__ b_ih)
{
    extern __shared__ char sm[];
    const unsigned sb = smem_u32(sm);

    const int tid = threadIdx.x;
    const size_t mbase = (size_t)blockIdx.y * 128;
    const int nbase = blockIdx.x * 64;

    // ---- stage A = x tile [128 x 128] split ----
#pragma unroll
    for (int c = tid; c < 128 * 16; c += 256) {
        int r = c >> 4, ch = c & 15;
        const float* xp = x + (mbase + r) * D_IN + ch * 8;
        float v[8];
        *reinterpret_cast<float4*>(v)     = *reinterpret_cast<const float4*>(xp);
        *reinterpret_cast<float4*>(v + 4) = *reinterpret_cast<const float4*>(xp + 4);
        uint4 hi, lo; split8(v, hi, lo);
        unsigned off = toff128(r, ch);
        *reinterpret_cast<uint4*>(sm + GI_SAHI + off) = hi;
        *reinterpret_cast<uint4*>(sm + GI_SALO + off) = lo;
    }
    // ---- stage B = W_ih slice [64 x 128] split ----
#pragma unroll
    for (int c = tid; c < 64 * 16; c += 256) {
        int r = c >> 4, ch = c & 15;
        const float* wp = W_ih + (size_t)(nbase + r) * D_IN + ch * 8;
        float v[8];
        *reinterpret_cast<float4*>(v)     = *reinterpret_cast<const float4*>(wp);
        *reinterpret_cast<float4*>(v + 4) = *reinterpret_cast<const float4*>(wp + 4);
        uint4 hi, lo; split8(v, hi, lo);
        unsigned off = toff128(r, ch);
        *reinterpret_cast<uint4*>(sm + GI_SBHI + off) = hi;
        *reinterpret_cast<uint4*>(sm + GI_SBLO + off) = lo;
    }
    __syncthreads();

    const int lane = tid & 31;
    const int w = tid >> 5;
    const int wm = w & 3;             // M: rows wm*32..+31
    const int wn = w >> 2;            // N: cols wn*32..+31
    const int ra    = (lane & 7) + ((lane & 8) ? 8 : 0);
    const int parA  = (lane >> 4) & 1;
    const int rowA0 = wm * 32 + ra;   // first m16 tile; second = +16
    const int rbrel = (lane & 7) + (((lane >> 4) & 1) ? 8 : 0);
    const int parB  = (lane >> 3) & 1;
    const int rowB0 = wn * 32 + rbrel;        // n16 group p=0
    const int rowB1 = rowB0 + 16;             // p=1

    float acc[2][4][4] = {};   // [m16 i][n8 j: p*2+q][frag]

#pragma unroll
    for (int ks = 0; ks < 8; ks++) {
        const int kc = ks * 2;
        unsigned ah0[4], ah1[4], al0[4], al1[4];
        {
            unsigned o0 = (unsigned)rowA0 * 256u + (unsigned)(((kc + parA) ^ (rowA0 & 7)) << 4);
            unsigned o1 = (unsigned)(rowA0 + 16) * 256u + (unsigned)(((kc + parA) ^ (rowA0 & 7)) << 4);
            LDM4(ah0, sb + GI_SAHI + o0);
            LDM4(ah1, sb + GI_SAHI + o1);
            LDM4(al0, sb + GI_SALO + o0);
            LDM4(al1, sb + GI_SALO + o1);
        }
        unsigned bh0[4], bh1[4], bl0[4], bl1[4];
        {
            unsigned o0 = (unsigned)rowB0 * 256u + (unsigned)(((kc + parB) ^ (rowB0 & 7)) << 4);
            unsigned o1 = (unsigned)rowB1 * 256u + (unsigned)(((kc + parB) ^ (rowB1 & 7)) << 4);
            LDM4(bh0, sb + GI_SBHI + o0);
            LDM4(bh1, sb + GI_SBHI + o1);
            LDM4(bl0, sb + GI_SBLO + o0);
            LDM4(bl1, sb + GI_SBLO + o1);
        }
        // hi*hi
        MMA16816(acc[0][0], ah0, bh0[0], bh0[1]); MMA16816(acc[0][1], ah0, bh0[2], bh0[3]);
        MMA16816(acc[0][2], ah0, bh1[0], bh1[1]); MMA16816(acc[0][3], ah0, bh1[2], bh1[3]);
        MMA16816(acc[1][0], ah1, bh0[0], bh0[1]); MMA16816(acc[1][1], ah1, bh0[2], bh0[3]);
        MMA16816(acc[1][2], ah1, bh1[0], bh1[1]); MMA16816(acc[1][3], ah1, bh1[2], bh1[3]);
        // hi*lo
        MMA16816(acc[0][0], ah0, bl0[0], bl0[1]); MMA16816(acc[0][1], ah0, bl0[2], bl0[3]);
        MMA16816(acc[0][2], ah0, bl1[0], bl1[1]); MMA16816(acc[0][3], ah0, bl1[2], bl1[3]);
        MMA16816(acc[1][0], ah1, bl0[0], bl0[1]); MMA16816(acc[1][1], ah1, bl0[2], bl0[3]);
        MMA16816(acc[1][2], ah1, bl1[0], bl1[1]); MMA16816(acc[1][3], ah1, bl1[2], bl1[3]);
        // lo*hi
        MMA16816(acc[0][0], al0, bh0[0], bh0[1]); MMA16816(acc[0][1], al0, bh0[2], bh0[3]);
        MMA16816(acc[0][2], al0, bh1[0], bh1[1]); MMA16816(acc[0][3], al0, bh1[2], bh1[3]);
        MMA16816(acc[1][0], al1, bh0[0], bh0[1]); MMA16816(acc[1][1], al1, bh0[2], bh0[3]);
        MMA16816(acc[1][2], al1, bh1[0], bh1[1]); MMA16816(acc[1][3], al1, bh1[2], bh1[3]);
    }

    // ---- epilogue: + bias, store fp32 ----
    const int tr = lane >> 2;
    const int tc = (lane & 3) * 2;
#pragma unroll
    for (int i = 0; i < 2; i++) {
#pragma unroll
        for (int jn = 0; jn < 4; jn++) {
            const int col = nbase + wn * 32 + (jn >> 1) * 16 + (jn & 1) * 8 + tc;
            float2 bias = *reinterpret_cast<const float2*>(b_ih + col);
            const size_t row0 = mbase + wm * 32 + i * 16 + tr;
            float2 v0 = make_float2(acc[i][jn][0] + bias.x, acc[i][jn][1] + bias.y);
            float2 v1 = make_float2(acc[i][jn][2] + bias.x, acc[i][jn][3] + bias.y);
            *reinterpret_cast<float2*>(g_gi + row0 * G3 + col)       = v0;
            *reinterpret_cast<float2*>(g_gi + (row0 + 8) * G3 + col) = v1;
        }
    }
}

// ---------------------------------------------------------------------------
// Grid barrier
// ---------------------------------------------------------------------------
__device__ __forceinline__ void grid_barrier(unsigned target)
{
    __syncthreads();
    __threadfence();
    __syncthreads();
    if (threadIdx.x == 0) {
        unsigned old = atomicInc(&g_bar_count, SC_GRID - 1);
        if (old == SC_GRID - 1) {
            g_bar_phase = target;
        } else {
            while (g_bar_phase != target) { }
        }
    }
    __syncthreads();
}

// ---------------------------------------------------------------------------
// Persistent GRU scan via mma.sync bf16 (3-term split, fp32 accum).
// 128 CTAs = 16 b-tiles(64) x 8 j-tiles(32).   gh[64 x 96] = A[64x256] B^T
// ---------------------------------------------------------------------------
#define S_BIAS 0u
#define S_GH   512u           // 64 x 104 fp32 = 26624 B
#define S_AHI  28672u         // 64 x 256 bf16 = 32768 B
#define S_ALO  61440u
#define S_WHI  94208u         // 96 x 256 bf16 = 49152 B
#define S_WLO  143360u
#define SMEM_SCAN 192512
#define GH_STR 104

__global__ void __launch_bounds__(256, 1)
gru_scan_mma(const float* __restrict__ h0,
             const float* __restrict__ masks,
             const float* __restrict__ W_hh,
             const float* __restrict__ b_hh,
             float* __restrict__ out)
{
    extern __shared__ char smem[];
    const unsigned sbase = smem_u32(smem);
    float* sbias = reinterpret_cast<float*>(smem + S_BIAS);
    float* sgh   = reinterpret_cast<float*>(smem + S_GH);

    const int tid = threadIdx.x;
    const int bi = blockIdx.x >> 3;
    const int ji = blockIdx.x & 7;
    const int b0 = bi * 64;
    const int j0 = ji * 32;

    const unsigned bar_base = g_bar_phase;

    for (int c = tid; c < 96 * 32; c += 256) {
        int r  = c >> 5;
        int ch = c & 31;
        int grow = (r >> 5) * H_SZ + j0 + (r & 31);
        float v[8];
        *reinterpret_cast<float4*>(v)     = *reinterpret_cast<const float4*>(W_hh + (size_t)grow * H_SZ + ch * 8);
        *reinterpret_cast<float4*>(v + 4) = *reinterpret_cast<const float4*>(W_hh + (size_t)grow * H_SZ + ch * 8 + 4);
        uint4 hi, lo;
        split8(v, hi, lo);
        unsigned off = toff(r, ch);
        *reinterpret_cast<uint4*>(smem + S_WHI + off) = hi;
        *reinterpret_cast<uint4*>(smem + S_WLO + off) = lo;
    }
    if (tid < 96) sbias[tid] = b_hh[(tid >> 5) * H_SZ + j0 + (tid & 31)];

    const int lane = tid & 31;
    const int w = tid >> 5;
    const int wm = w & 3;
    const int wn = w >> 2;
    const int rowA = wm * 16 + (lane & 7) + ((lane & 8) ? 8 : 0);
    const int parA = (lane >> 4) & 1;
    const int rbrel = (lane & 7) + (((lane >> 4) & 1) ? 8 : 0);
    const int parB = (lane >> 3) & 1;
    int rowB[3];
#pragma unroll
    for (int p = 0; p < 3; p++) rowB[p] = wn * 48 + p * 16 + rbrel;

    const int gr = tid >> 2;
    const int gq = tid & 3;
    const int jj0 = gq * 8;
    const int b = b0 + gr;
    const int jg = j0 + jj0;

    __syncthreads();

    for (int t = 0; t < T_STEPS; t++) {
        const float* mrow = masks + (size_t)t * B_SZ + b0;

        if (t == 0) {
#pragma unroll
            for (int c = tid; c < 64 * 32; c += 256) {
                int r = c >> 5, ch = c & 31;
                float m = __ldg(mrow + r);
                const float* hp = h0 + (size_t)(b0 + r) * H_SZ + ch * 8;
                float v[8];
                *reinterpret_cast<float4*>(v)     = *reinterpret_cast<const float4*>(hp);
                *reinterpret_cast<float4*>(v + 4) = *reinterpret_cast<const float4*>(hp + 4);
#pragma unroll
                for (int i = 0; i < 8; i++) v[i] *= m;
                uint4 hi, lo;
                split8(v, hi, lo);
                unsigned off = toff(r, ch);
                *reinterpret_cast<uint4*>(smem + S_AHI + off) = hi;
                *reinterpret_cast<uint4*>(smem + S_ALO + off) = lo;
            }
        } else {
            const int pb = (t - 1) & 1;
#pragma unroll
            for (int c = tid; c < 64 * 32; c += 256) {
                int r = c >> 5, ch = c & 31;
                float m = __ldg(mrow + r);
                size_t gidx = ((size_t)(b0 + r) * H_SZ + ch * 8) >> 3;
                uint4 hi = __ldcg(reinterpret_cast<const uint4*>(g_hhi[pb]) + gidx);
                uint4 lo = __ldcg(reinterpret_cast<const uint4*>(g_hlo[pb]) + gidx);
                if (m == 0.0f) { hi = make_uint4(0,0,0,0); lo = make_uint4(0,0,0,0); }
                unsigned off = toff(r, ch);
                *reinterpret_cast<uint4*>(smem + S_AHI + off) = hi;
                *reinterpret_cast<uint4*>(smem + S_ALO + off) = lo;
            }
        }
        __syncthreads();

        float gir[8], giz[8], gin[8];
        {
            const float* gib = g_gi + ((size_t)t * B_SZ + b) * G3 + jg;
            *reinterpret_cast<float4*>(gir)     = __ldcs(reinterpret_cast<const float4*>(gib));
            *reinterpret_cast<float4*>(gir + 4) = __ldcs(reinterpret_cast<const float4*>(gib + 4));
            *reinterpret_cast<float4*>(giz)     = __ldcs(reinterpret_cast<const float4*>(gib + H_SZ));
            *reinterpret_cast<float4*>(giz + 4) = __ldcs(reinterpret_cast<const float4*>(gib + H_SZ + 4));
            *reinterpret_cast<float4*>(gin)     = __ldcs(reinterpret_cast<const float4*>(gib + 2 * H_SZ));
            *reinterpret_cast<float4*>(gin + 4) = __ldcs(reinterpret_cast<const float4*>(gib + 2 * H_SZ + 4));
        }

        float acc[6][4] = {};
#pragma unroll 4
        for (int ks = 0; ks < 16; ks++) {
            const int kc = ks * 2;
            unsigned ahi[4], alo[4];
            unsigned aoffs = (unsigned)rowA * 512u + (unsigned)(((kc + parA) ^ (rowA & 7)) << 4);
            LDM4(ahi, sbase + S_AHI + aoffs);
            LDM4(alo, sbase + S_ALO + aoffs);
#pragma unroll
            for (int p = 0; p < 3; p++) {
                unsigned boffs = (unsigned)rowB[p] * 512u + (unsigned)(((kc + parB) ^ (rowB[p] & 7)) << 4);
                unsigned bh[4], bl[4];
                LDM4(bh, sbase + S_WHI + boffs);
                LDM4(bl, sbase + S_WLO + boffs);
                MMA16816(acc[2 * p],     ahi, bh[0], bh[1]);
                MMA16816(acc[2 * p + 1], ahi, bh[2], bh[3]);
                MMA16816(acc[2 * p],     ahi, bl[0], bl[1]);
                MMA16816(acc[2 * p + 1], ahi, bl[2], bl[3]);
                MMA16816(acc[2 * p],     alo, bh[0], bh[1]);
                MMA16816(acc[2 * p + 1], alo, bh[2], bh[3]);
            }
        }

        {
            const int r0 = wm * 16 + lane / 4;
            const int cb = wn * 48 + (lane % 4) * 2;
#pragma unroll
            for (int i = 0; i < 6; i++) {
                const int col = cb + (i >> 1) * 16 + (i & 1) * 8;
                *reinterpret_cast<float2*>(&sgh[r0 * GH_STR + col])       = make_float2(acc[i][0], acc[i][1]);
                *reinterpret_cast<float2*>(&sgh[(r0 + 8) * GH_STR + col]) = make_float2(acc[i][2], acc[i][3]);
            }
        }
        __syncthreads();

        {
            float ghr[8], ghz[8], ghn[8], hpv[8], hv[8];
            *reinterpret_cast<float4*>(ghr)     = *reinterpret_cast<const float4*>(&sgh[gr * GH_STR + jj0]);
            *reinterpret_cast<float4*>(ghr + 4) = *reinterpret_cast<const float4*>(&sgh[gr * GH_STR + jj0 + 4]);
            *reinterpret_cast<float4*>(ghz)     = *reinterpret_cast<const float4*>(&sgh[gr * GH_STR + 32 + jj0]);
            *reinterpret_cast<float4*>(ghz + 4) = *reinterpret_cast<const float4*>(&sgh[gr * GH_STR + 32 + jj0 + 4]);
            *reinterpret_cast<float4*>(ghn)     = *reinterpret_cast<const float4*>(&sgh[gr * GH_STR + 64 + jj0]);
            *reinterpret_cast<float4*>(ghn + 4) = *reinterpret_cast<const float4*>(&sgh[gr * GH_STR + 64 + jj0 + 4]);

            {
                unsigned off = toff(gr, jg >> 3);
                uint4 hi = *reinterpret_cast<const uint4*>(smem + S_AHI + off);
                uint4 lo = *reinterpret_cast<const uint4*>(smem + S_ALO + off);
                unsigned hu[4] = {hi.x, hi.y, hi.z, hi.w};
                unsigned lu[4] = {lo.x, lo.y, lo.z, lo.w};
#pragma unroll
                for (int q = 0; q < 4; q++) unpack2(hu[q], lu[q], hpv[2 * q], hpv[2 * q + 1]);
            }

#pragma unroll
            for (int i = 0; i < 8; i++) {
                float br = sbias[jj0 + i];
                float bz = sbias[32 + jj0 + i];
                float bn = sbias[64 + jj0 + i];
                float r = fast_sigmoid(gir[i] + ghr[i] + br);
                float z = fast_sigmoid(giz[i] + ghz[i] + bz);
                float n = fast_tanh(gin[i] + r * (ghn[i] + bn));
                hv[i] = (1.0f - z) * n + z * hpv[i];
            }

            float* yp = out + ((size_t)t * B_SZ + b) * H_SZ + jg;
            *reinterpret_cast<float4*>(yp)     = make_float4(hv[0], hv[1], hv[2], hv[3]);
            *reinterpret_cast<float4*>(yp + 4) = make_float4(hv[4], hv[5], hv[6], hv[7]);

            uint4 oh, ol;
            split8(hv, oh, ol);
            const int cb2 = t & 1;
            size_t gidx = ((size_t)b * H_SZ + jg) >> 3;
            reinterpret_cast<uint4*>(g_hhi[cb2])[gidx] = oh;
            reinterpret_cast<uint4*>(g_hlo[cb2])[gidx] = ol;

            if (t == T_STEPS - 1) {
                float* fp = out + (size_t)T_STEPS * B_SZ * H_SZ + (size_t)b * H_SZ + jg;
                *reinterpret_cast<float4*>(fp)     = make_float4(hv[0], hv[1], hv[2], hv[3]);
                *reinterpret_cast<float4*>(fp + 4) = make_float4(hv[4], hv[5], hv[6], hv[7]);
            }
        }

        grid_barrier(bar_base + (unsigned)t + 1u);
    }
}

// ---------------------------------------------------------------------------
// In-place LayerNorm over last dim (256). One warp per (t,b) row.
// ---------------------------------------------------------------------------
__global__ void __launch_bounds__(256)
ln_kernel(float* __restrict__ y,
          const float* __restrict__ lw,
          const float* __restrict__ lb)
{
    const int lane = threadIdx.x & 31;
    const int warp = threadIdx.x >> 5;
    const size_t row = (size_t)blockIdx.x * 8 + warp;
    float* p = y + row * H_SZ;

    float4 v0 = *reinterpret_cast<const float4*>(p + lane * 4);
    float4 v1 = *reinterpret_cast<const float4*>(p + 128 + lane * 4);

    float s = v0.x + v0.y + v0.z + v0.w + v1.x + v1.y + v1.z + v1.w;
#pragma unroll
    for (int o = 16; o; o >>= 1) s += __shfl_xor_sync(0xffffffffu, s, o);
    const float mu = s * (1.0f / 256.0f);

    float q = (v0.x - mu) * (v0.x - mu) + (v0.y - mu) * (v0.y - mu)
            + (v0.z - mu) * (v0.z - mu) + (v0.w - mu) * (v0.w - mu)
            + (v1.x - mu) * (v1.x - mu) + (v1.y - mu) * (v1.y - mu)
            + (v1.z - mu) * (v1.z - mu) + (v1.w - mu) * (v1.w - mu);
#pragma unroll
    for (int o = 16; o; o >>= 1) q += __shfl_xor_sync(0xffffffffu, q, o);
    const float rs = rsqrtf(q * (1.0f / 256.0f) + 1e-5f);

    float4 w0 = *reinterpret_cast<const float4*>(lw + lane * 4);
    float4 w1 = *reinterpret_cast<const float4*>(lw + 128 + lane * 4);
    float4 c0 = *reinterpret_cast<const float4*>(lb + lane * 4);
    float4 c1 = *reinterpret_cast<const float4*>(lb + 128 + lane * 4);

    v0.x = (v0.x - mu) * rs * w0.x + c0.x;
    v0.y = (v0.y - mu) * rs * w0.y + c0.y;
    v0.z = (v0.z - mu) * rs * w0.z + c0.z;
    v0.w = (v0.w - mu) * rs * w0.w + c0.w;
    v1.x = (v1.x - mu) * rs * w1.x + c1.x;
    v1.y = (v1.y - mu) * rs * w1.y + c1.y;
    v1.z = (v1.z - mu) * rs * w1.z + c1.z;
    v1.w = (v1.w - mu) * rs * w1.w + c1.w;

    *reinterpret_cast<float4*>(p + lane * 4) = v0;
    *reinterpret_cast<float4*>(p + 128 + lane * 4) = v1;
}

// ---------------------------------------------------------------------------
extern "C" void kernel_launch(void* const* d_in, const int* in_sizes, int n_in,
                              void* d_out, int out_size)
{
    const float* x     = (const float*)d_in[0];
    const float* h0    = (const float*)d_in[1];
    const float* masks = (const float*)d_in[2];
    const float* W_ih  = (const float*)d_in[3];
    const float* W_hh  = (const float*)d_in[4];
    const float* b_ih  = (const float*)d_in[5];
    const float* b_hh  = (const float*)d_in[6];
    const float* ln_w  = (const float*)d_in[7];
    const float* ln_b  = (const float*)d_in[8];
    float* out = (float*)d_out;

    (void)in_sizes; (void)n_in; (void)out_size;

    cudaFuncSetAttribute(gi_mma, cudaFuncAttributeMaxDynamicSharedMemorySize, GI_SMEM);
    cudaFuncSetAttribute(gru_scan_mma, cudaFuncAttributeMaxDynamicSharedMemorySize, SMEM_SCAN);

    dim3 gA(G3 / 64, (T_STEPS * B_SZ) / 128);   // (12, 4096)
    gi_mma<<<gA, 256, GI_SMEM>>>(x, W_ih, b_ih);

    gru_scan_mma<<<SC_GRID, 256, SMEM_SCAN>>>(h0, masks, W_hh, b_hh, out);

    ln_kernel<<<(T_STEPS * B_SZ) / 8, 256>>>(out, ln_w, ln_b);
}

// round 6
// speedup vs baseline: 2.8316x; 1.0658x over previous
#include <cuda_runtime.h>
#include <cuda_bf16.h>
#include <cstdint>

#define T_STEPS 512
#define B_SZ    1024
#define D_IN    128
#define H_SZ    256
#define G3      (3 * H_SZ)   // 768

#define SC_GRID 128          // 16 b-tiles x 8 j-tiles, 1 CTA/SM, 512 thr

// ---------------------------------------------------------------------------
// Scratch (device globals)
// ---------------------------------------------------------------------------
__device__ float g_gi[(size_t)T_STEPS * B_SZ * G3];
// h exchange: per (ping, group) one 64x256 bf16 tile image, hi plane then lo
// plane, already in the swizzled smem layout (pure byte copy to stage).
__device__ __align__(16) unsigned char g_htile[2][16][2 * 32768];

struct GroupBar { unsigned cnt; unsigned phase; unsigned pad[30]; };
__device__ GroupBar g_gbar[16];

// ---------------------------------------------------------------------------
// Helpers
// ---------------------------------------------------------------------------
__device__ __forceinline__ unsigned smem_u32(const void* p) {
    unsigned a;
    asm("{ .reg .u64 t; cvta.to.shared.u64 t, %1; cvt.u32.u64 %0, t; }" : "=r"(a) : "l"(p));
    return a;
}

// 512 B/row tile (256 bf16), 16B-chunk XOR swizzle (scan tiles)
__device__ __forceinline__ unsigned toff(int row, int chunk) {
    return (unsigned)row * 512u + (unsigned)((chunk ^ (row & 7)) << 4);
}
// 256 B/row variant (gi tiles, K=128)
__device__ __forceinline__ unsigned toff128(int row, int chunk) {
    return (unsigned)row * 256u + (unsigned)((chunk ^ (row & 7)) << 4);
}

__device__ __forceinline__ uint4 pack8(const unsigned s[8]) {
    return make_uint4(s[0] | (s[1] << 16), s[2] | (s[3] << 16),
                      s[4] | (s[5] << 16), s[6] | (s[7] << 16));
}

__device__ __forceinline__ void split8(const float v[8], uint4& hi, uint4& lo) {
    unsigned h[8], l[8];
#pragma unroll
    for (int i = 0; i < 8; i++) {
        __nv_bfloat16 bh = __float2bfloat16(v[i]);
        float fh = __bfloat162float(bh);
        __nv_bfloat16 bl = __float2bfloat16(v[i] - fh);
        h[i] = (unsigned)__bfloat16_as_ushort(bh);
        l[i] = (unsigned)__bfloat16_as_ushort(bl);
    }
    hi = pack8(h); lo = pack8(l);
}

__device__ __forceinline__ void split4(const float v[4], uint2& hi, uint2& lo) {
    unsigned h[4], l[4];
#pragma unroll
    for (int i = 0; i < 4; i++) {
        __nv_bfloat16 bh = __float2bfloat16(v[i]);
        float fh = __bfloat162float(bh);
        __nv_bfloat16 bl = __float2bfloat16(v[i] - fh);
        h[i] = (unsigned)__bfloat16_as_ushort(bh);
        l[i] = (unsigned)__bfloat16_as_ushort(bl);
    }
    hi = make_uint2(h[0] | (h[1] << 16), h[2] | (h[3] << 16));
    lo = make_uint2(l[0] | (l[1] << 16), l[2] | (l[3] << 16));
}

__device__ __forceinline__ void unpack2(unsigned hi, unsigned lo, float& f0, float& f1) {
    f0 = __uint_as_float(hi << 16)         + __uint_as_float(lo << 16);
    f1 = __uint_as_float(hi & 0xffff0000u) + __uint_as_float(lo & 0xffff0000u);
}

__device__ __forceinline__ float fast_sigmoid(float x) {
    return __fdividef(1.0f, 1.0f + __expf(-x));
}
__device__ __forceinline__ float fast_tanh(float x) {
    return 1.0f - 2.0f * __fdividef(1.0f, __expf(2.0f * x) + 1.0f);
}

#define LDM4(r, a)                                                             \
    asm volatile("ldmatrix.sync.aligned.m8n8.x4.shared.b16 {%0,%1,%2,%3}, [%4];" \
        : "=r"((r)[0]), "=r"((r)[1]), "=r"((r)[2]), "=r"((r)[3]) : "r"(a))

#define MMA16816(c, a, b0v, b1v)                                               \
    asm volatile("mma.sync.aligned.m16n8k16.row.col.f32.bf16.bf16.f32 "        \
        "{%0,%1,%2,%3}, {%4,%5,%6,%7}, {%8,%9}, {%0,%1,%2,%3};"                \
        : "+f"((c)[0]), "+f"((c)[1]), "+f"((c)[2]), "+f"((c)[3])               \
        : "r"((a)[0]), "r"((a)[1]), "r"((a)[2]), "r"((a)[3]), "r"(b0v), "r"(b1v))

#define CP_ASYNC16(dst, src)                                                   \
    asm volatile("cp.async.cg.shared.global [%0], [%1], 16;" :: "r"(dst), "l"(src))

// ---------------------------------------------------------------------------
// Kernel A: gi = x @ W_ih^T + b_ih  via bf16-split mma.sync (unchanged R5)
// ---------------------------------------------------------------------------
#define GI_SAHI 0u
#define GI_SALO 32768u
#define GI_SBHI 65536u
#define GI_SBLO 81920u
#define GI_SMEM 98304

__global__ void __launch_bounds__(256, 2)
gi_mma(const float* __restrict__ x,
       const float* __restrict__ W_ih,
       const float* __restrict__ b_ih)
{
    extern __shared__ char sm[];
    const unsigned sb = smem_u32(sm);

    const int tid = threadIdx.x;
    const size_t mbase = (size_t)blockIdx.y * 128;
    const int nbase = blockIdx.x * 64;

#pragma unroll
    for (int c = tid; c < 128 * 16; c += 256) {
        int r = c >> 4, ch = c & 15;
        const float* xp = x + (mbase + r) * D_IN + ch * 8;
        float v[8];
        *reinterpret_cast<float4*>(v)     = *reinterpret_cast<const float4*>(xp);
        *reinterpret_cast<float4*>(v + 4) = *reinterpret_cast<const float4*>(xp + 4);
        uint4 hi, lo; split8(v, hi, lo);
        unsigned off = toff128(r, ch);
        *reinterpret_cast<uint4*>(sm + GI_SAHI + off) = hi;
        *reinterpret_cast<uint4*>(sm + GI_SALO + off) = lo;
    }
#pragma unroll
    for (int c = tid; c < 64 * 16; c += 256) {
        int r = c >> 4, ch = c & 15;
        const float* wp = W_ih + (size_t)(nbase + r) * D_IN + ch * 8;
        float v[8];
        *reinterpret_cast<float4*>(v)     = *reinterpret_cast<const float4*>(wp);
        *reinterpret_cast<float4*>(v + 4) = *reinterpret_cast<const float4*>(wp + 4);
        uint4 hi, lo; split8(v, hi, lo);
        unsigned off = toff128(r, ch);
        *reinterpret_cast<uint4*>(sm + GI_SBHI + off) = hi;
        *reinterpret_cast<uint4*>(sm + GI_SBLO + off) = lo;
    }
    __syncthreads();

    const int lane = tid & 31;
    const int w = tid >> 5;
    const int wm = w & 3;
    const int wn = w >> 2;
    const int ra    = (lane & 7) + ((lane & 8) ? 8 : 0);
    const int parA  = (lane >> 4) & 1;
    const int rowA0 = wm * 32 + ra;
    const int rbrel = (lane & 7) + (((lane >> 4) & 1) ? 8 : 0);
    const int parB  = (lane >> 3) & 1;
    const int rowB0 = wn * 32 + rbrel;
    const int rowB1 = rowB0 + 16;

    float acc[2][4][4] = {};

#pragma unroll
    for (int ks = 0; ks < 8; ks++) {
        const int kc = ks * 2;
        unsigned ah0[4], ah1[4], al0[4], al1[4];
        {
            unsigned o0 = (unsigned)rowA0 * 256u + (unsigned)(((kc + parA) ^ (rowA0 & 7)) << 4);
            unsigned o1 = (unsigned)(rowA0 + 16) * 256u + (unsigned)(((kc + parA) ^ (rowA0 & 7)) << 4);
            LDM4(ah0, sb + GI_SAHI + o0);
            LDM4(ah1, sb + GI_SAHI + o1);
            LDM4(al0, sb + GI_SALO + o0);
            LDM4(al1, sb + GI_SALO + o1);
        }
        unsigned bh0[4], bh1[4], bl0[4], bl1[4];
        {
            unsigned o0 = (unsigned)rowB0 * 256u + (unsigned)(((kc + parB) ^ (rowB0 & 7)) << 4);
            unsigned o1 = (unsigned)rowB1 * 256u + (unsigned)(((kc + parB) ^ (rowB1 & 7)) << 4);
            LDM4(bh0, sb + GI_SBHI + o0);
            LDM4(bh1, sb + GI_SBHI + o1);
            LDM4(bl0, sb + GI_SBLO + o0);
            LDM4(bl1, sb + GI_SBLO + o1);
        }
        MMA16816(acc[0][0], ah0, bh0[0], bh0[1]); MMA16816(acc[0][1], ah0, bh0[2], bh0[3]);
        MMA16816(acc[0][2], ah0, bh1[0], bh1[1]); MMA16816(acc[0][3], ah0, bh1[2], bh1[3]);
        MMA16816(acc[1][0], ah1, bh0[0], bh0[1]); MMA16816(acc[1][1], ah1, bh0[2], bh0[3]);
        MMA16816(acc[1][2], ah1, bh1[0], bh1[1]); MMA16816(acc[1][3], ah1, bh1[2], bh1[3]);
        MMA16816(acc[0][0], ah0, bl0[0], bl0[1]); MMA16816(acc[0][1], ah0, bl0[2], bl0[3]);
        MMA16816(acc[0][2], ah0, bl1[0], bl1[1]); MMA16816(acc[0][3], ah0, bl1[2], bl1[3]);
        MMA16816(acc[1][0], ah1, bl0[0], bl0[1]); MMA16816(acc[1][1], ah1, bl0[2], bl0[3]);
        MMA16816(acc[1][2], ah1, bl1[0], bl1[1]); MMA16816(acc[1][3], ah1, bl1[2], bl1[3]);
        MMA16816(acc[0][0], al0, bh0[0], bh0[1]); MMA16816(acc[0][1], al0, bh0[2], bh0[3]);
        MMA16816(acc[0][2], al0, bh1[0], bh1[1]); MMA16816(acc[0][3], al0, bh1[2], bh1[3]);
        MMA16816(acc[1][0], al1, bh0[0], bh0[1]); MMA16816(acc[1][1], al1, bh0[2], bh0[3]);
        MMA16816(acc[1][2], al1, bh1[0], bh1[1]); MMA16816(acc[1][3], al1, bh1[2], bh1[3]);
    }

    const int tr = lane >> 2;
    const int tc = (lane & 3) * 2;
#pragma unroll
    for (int i = 0; i < 2; i++) {
#pragma unroll
        for (int jn = 0; jn < 4; jn++) {
            const int col = nbase + wn * 32 + (jn >> 1) * 16 + (jn & 1) * 8 + tc;
            float2 bias = *reinterpret_cast<const float2*>(b_ih + col);
            const size_t row0 = mbase + wm * 32 + i * 16 + tr;
            float2 v0 = make_float2(acc[i][jn][0] + bias.x, acc[i][jn][1] + bias.y);
            float2 v1 = make_float2(acc[i][jn][2] + bias.x, acc[i][jn][3] + bias.y);
            *reinterpret_cast<float2*>(g_gi + row0 * G3 + col)       = v0;
            *reinterpret_cast<float2*>(g_gi + (row0 + 8) * G3 + col) = v1;
        }
    }
}

// ---------------------------------------------------------------------------
// Persistent GRU scan: 512 thr, split-K mma, per-group barriers, cp.async
// staging, mask folded into gate phase.
// smem: bias 512 | gh0 26624 | gh1 26624 | A_hi 32768 | A_lo 32768 |
//       W_hi 49152 | W_lo 49152   => 217600 B
// ---------------------------------------------------------------------------
#define S_BIAS 0u
#define S_GH0  512u
#define S_GH1  27136u
#define S_AHI  53760u
#define S_ALO  86528u
#define S_WHI  119296u
#define S_WLO  168448u
#define SMEM_SCAN 217600
#define GH_STR 104
#define GH_HALF 6656   // floats between gh0 and gh1

__global__ void __launch_bounds__(512, 1)
gru_scan_mma(const float* __restrict__ h0,
             const float* __restrict__ masks,
             const float* __restrict__ W_hh,
             const float* __restrict__ b_hh,
             float* __restrict__ out)
{
    extern __shared__ char smem[];
    const unsigned sbase = smem_u32(smem);
    float* sbias = reinterpret_cast<float*>(smem + S_BIAS);
    float* sgh   = reinterpret_cast<float*>(smem + S_GH0);

    const int tid = threadIdx.x;
    const int bi = blockIdx.x >> 3;   // group 0..15
    const int ji = blockIdx.x & 7;
    const int b0 = bi * 64;
    const int j0 = ji * 32;

    // phase snapshot (safe: phase only advances after ALL group CTAs arrive)
    unsigned bar_base;
    asm volatile("ld.acquire.gpu.global.u32 %0, [%1];"
                 : "=r"(bar_base) : "l"(&g_gbar[bi].phase));

    // ---- stage W_hh slice split to bf16 ----
    for (int c = tid; c < 96 * 32; c += 512) {
        int r  = c >> 5;
        int ch = c & 31;
        int grow = (r >> 5) * H_SZ + j0 + (r & 31);
        float v[8];
        *reinterpret_cast<float4*>(v)     = *reinterpret_cast<const float4*>(W_hh + (size_t)grow * H_SZ + ch * 8);
        *reinterpret_cast<float4*>(v + 4) = *reinterpret_cast<const float4*>(W_hh + (size_t)grow * H_SZ + ch * 8 + 4);
        uint4 hi, lo;
        split8(v, hi, lo);
        unsigned off = toff(r, ch);
        *reinterpret_cast<uint4*>(smem + S_WHI + off) = hi;
        *reinterpret_cast<uint4*>(smem + S_WLO + off) = lo;
    }
    if (tid < 96) sbias[tid] = b_hh[(tid >> 5) * H_SZ + j0 + (tid & 31)];

    // ---- MMA mapping (16 warps: 4 m x 2 n x 2 k-half) ----
    const int lane = tid & 31;
    const int w = tid >> 5;
    const int wm = w & 3;
    const int wn = (w >> 2) & 1;
    const int kh = w >> 3;
    const int rowA = wm * 16 + (lane & 7) + ((lane & 8) ? 8 : 0);
    const int parA = (lane >> 4) & 1;
    const int rbrel = (lane & 7) + (((lane >> 4) & 1) ? 8 : 0);
    const int parB = (lane >> 3) & 1;
    int rowB[3];
#pragma unroll
    for (int p = 0; p < 3; p++) rowB[p] = wn * 48 + p * 16 + rbrel;
    float* sghk = sgh + kh * GH_HALF;

    // ---- gate mapping: thread handles (row gr, 4 j) ----
    const int gr = tid >> 3;
    const int gq = tid & 7;
    const int jj0 = gq * 4;
    const int b = b0 + gr;
    const int jg = j0 + jj0;
    const unsigned hpo = toff(gr, jg >> 3) + (unsigned)((jg & 7) << 1);

    __syncthreads();

    for (int t = 0; t < T_STEPS; t++) {
        // ---- stage h tile (unmasked, pre-split, pre-swizzled) ----
        if (t == 0) {
            for (int c = tid; c < 64 * 32; c += 512) {
                int r = c >> 5, ch = c & 31;
                const float* hp = h0 + (size_t)(b0 + r) * H_SZ + ch * 8;
                float v[8];
                *reinterpret_cast<float4*>(v)     = *reinterpret_cast<const float4*>(hp);
                *reinterpret_cast<float4*>(v + 4) = *reinterpret_cast<const float4*>(hp + 4);
                uint4 hi, lo;
                split8(v, hi, lo);
                unsigned off = toff(r, ch);
                *reinterpret_cast<uint4*>(smem + S_AHI + off) = hi;
                *reinterpret_cast<uint4*>(smem + S_ALO + off) = lo;
            }
        } else {
            const unsigned char* src = g_htile[(t - 1) & 1][bi];
#pragma unroll
            for (int c = tid; c < 4096; c += 512) {
                CP_ASYNC16(sbase + S_AHI + (unsigned)c * 16u, src + (size_t)c * 16);
            }
            asm volatile("cp.async.commit_group;");
        }

        // ---- gi + mask prefetch (overlaps cp.async / later MMA) ----
        float gir[4], giz[4], gin[4];
        {
            const float* gib = g_gi + ((size_t)t * B_SZ + b) * G3 + jg;
            *reinterpret_cast<float4*>(gir) = __ldcs(reinterpret_cast<const float4*>(gib));
            *reinterpret_cast<float4*>(giz) = __ldcs(reinterpret_cast<const float4*>(gib + H_SZ));
            *reinterpret_cast<float4*>(gin) = __ldcs(reinterpret_cast<const float4*>(gib + 2 * H_SZ));
        }
        const float m = __ldg(masks + (size_t)t * B_SZ + b);

        if (t != 0) {
            asm volatile("cp.async.wait_group 0;" ::: "memory");
        }
        __syncthreads();

        // ---- tensor GEMM: this warp does 8 k-steps of its k-half ----
        float acc[6][4] = {};
#pragma unroll
        for (int ks = 0; ks < 8; ks++) {
            const int kc = (kh * 8 + ks) * 2;
            unsigned ahi[4], alo[4];
            unsigned aoffs = (unsigned)rowA * 512u + (unsigned)(((kc + parA) ^ (rowA & 7)) << 4);
            LDM4(ahi, sbase + S_AHI + aoffs);
            LDM4(alo, sbase + S_ALO + aoffs);
#pragma unroll
            for (int p = 0; p < 3; p++) {
                unsigned boffs = (unsigned)rowB[p] * 512u + (unsigned)(((kc + parB) ^ (rowB[p] & 7)) << 4);
                unsigned bh[4], bl[4];
                LDM4(bh, sbase + S_WHI + boffs);
                LDM4(bl, sbase + S_WLO + boffs);
                MMA16816(acc[2 * p],     ahi, bh[0], bh[1]);
                MMA16816(acc[2 * p + 1], ahi, bh[2], bh[3]);
                MMA16816(acc[2 * p],     ahi, bl[0], bl[1]);
                MMA16816(acc[2 * p + 1], ahi, bl[2], bl[3]);
                MMA16816(acc[2 * p],     alo, bh[0], bh[1]);
                MMA16816(acc[2 * p + 1], alo, bh[2], bh[3]);
            }
        }

        // ---- accumulators -> smem partials ----
        {
            const int r0 = wm * 16 + lane / 4;
            const int cb = wn * 48 + (lane % 4) * 2;
#pragma unroll
            for (int i = 0; i < 6; i++) {
                const int col = cb + (i >> 1) * 16 + (i & 1) * 8;
                *reinterpret_cast<float2*>(&sghk[r0 * GH_STR + col])       = make_float2(acc[i][0], acc[i][1]);
                *reinterpret_cast<float2*>(&sghk[(r0 + 8) * GH_STR + col]) = make_float2(acc[i][2], acc[i][3]);
            }
        }
        __syncthreads();

        // ---- gates (mask folded: gh_masked = m*gh_raw, hp = m*h_raw) ----
        {
            float4 r0 = *reinterpret_cast<const float4*>(&sgh[gr * GH_STR + jj0]);
            float4 r1 = *reinterpret_cast<const float4*>(&sgh[GH_HALF + gr * GH_STR + jj0]);
            float4 z0 = *reinterpret_cast<const float4*>(&sgh[gr * GH_STR + 32 + jj0]);
            float4 z1 = *reinterpret_cast<const float4*>(&sgh[GH_HALF + gr * GH_STR + 32 + jj0]);
            float4 n0 = *reinterpret_cast<const float4*>(&sgh[gr * GH_STR + 64 + jj0]);
            float4 n1 = *reinterpret_cast<const float4*>(&sgh[GH_HALF + gr * GH_STR + 64 + jj0]);
            float ghr[4] = {r0.x + r1.x, r0.y + r1.y, r0.z + r1.z, r0.w + r1.w};
            float ghz[4] = {z0.x + z1.x, z0.y + z1.y, z0.z + z1.z, z0.w + z1.w};
            float ghn[4] = {n0.x + n1.x, n0.y + n1.y, n0.z + n1.z, n0.w + n1.w};

            float hpv[4];
            {
                uint2 hi = *reinterpret_cast<const uint2*>(smem + S_AHI + hpo);
                uint2 lo = *reinterpret_cast<const uint2*>(smem + S_ALO + hpo);
                unpack2(hi.x, lo.x, hpv[0], hpv[1]);
                unpack2(hi.y, lo.y, hpv[2], hpv[3]);
            }

            float hv[4];
#pragma unroll
            for (int i = 0; i < 4; i++) {
                float br = sbias[jj0 + i];
                float bz = sbias[32 + jj0 + i];
                float bn = sbias[64 + jj0 + i];
                float r = fast_sigmoid(gir[i] + m * ghr[i] + br);
                float z = fast_sigmoid(giz[i] + m * ghz[i] + bz);
                float n = fast_tanh(gin[i] + r * (m * ghn[i] + bn));
                hv[i] = (1.0f - z) * n + z * (m * hpv[i]);
            }

            float* yp = out + ((size_t)t * B_SZ + b) * H_SZ + jg;
            *reinterpret_cast<float4*>(yp) = make_float4(hv[0], hv[1], hv[2], hv[3]);

            // h exchange write: split, already-swizzled tile image
            uint2 oh, ol;
            split4(hv, oh, ol);
            unsigned char* dst = g_htile[t & 1][bi];
            *reinterpret_cast<uint2*>(dst + hpo)         = oh;
            *reinterpret_cast<uint2*>(dst + 32768 + hpo) = ol;

            if (t == T_STEPS - 1) {
                float* fp = out + (size_t)T_STEPS * B_SZ * H_SZ + (size_t)b * H_SZ + jg;
                *reinterpret_cast<float4*>(fp) = make_float4(hv[0], hv[1], hv[2], hv[3]);
            }
        }

        // ---- per-group barrier (8 CTAs): release-RMW + phase ----
        __syncthreads();
        if (tid == 0) {
            const unsigned target = bar_base + (unsigned)t + 1u;
            unsigned old;
            asm volatile("atom.add.acq_rel.gpu.global.u32 %0, [%1], 1;"
                         : "=r"(old) : "l"(&g_gbar[bi].cnt) : "memory");
            if ((old & 7u) == 7u) {
                asm volatile("st.release.gpu.global.u32 [%0], %1;"
                             :: "l"(&g_gbar[bi].phase), "r"(target) : "memory");
            } else {
                unsigned p;
                do {
                    asm volatile("ld.acquire.gpu.global.u32 %0, [%1];"
                                 : "=r"(p) : "l"(&g_gbar[bi].phase) : "memory");
                } while (p != target);
            }
        }
        __syncthreads();
    }
}

// ---------------------------------------------------------------------------
// In-place LayerNorm over last dim (256). One warp per (t,b) row.
// ---------------------------------------------------------------------------
__global__ void __launch_bounds__(256)
ln_kernel(float* __restrict__ y,
          const float* __restrict__ lw,
          const float* __restrict__ lb)
{
    const int lane = threadIdx.x & 31;
    const int warp = threadIdx.x >> 5;
    const size_t row = (size_t)blockIdx.x * 8 + warp;
    float* p = y + row * H_SZ;

    float4 v0 = *reinterpret_cast<const float4*>(p + lane * 4);
    float4 v1 = *reinterpret_cast<const float4*>(p + 128 + lane * 4);

    float s = v0.x + v0.y + v0.z + v0.w + v1.x + v1.y + v1.z + v1.w;
#pragma unroll
    for (int o = 16; o; o >>= 1) s += __shfl_xor_sync(0xffffffffu, s, o);
    const float mu = s * (1.0f / 256.0f);

    float q = (v0.x - mu) * (v0.x - mu) + (v0.y - mu) * (v0.y - mu)
            + (v0.z - mu) * (v0.z - mu) + (v0.w - mu) * (v0.w - mu)
            + (v1.x - mu) * (v1.x - mu) + (v1.y - mu) * (v1.y - mu)
            + (v1.z - mu) * (v1.z - mu) + (v1.w - mu) * (v1.w - mu);
#pragma unroll
    for (int o = 16; o; o >>= 1) q += __shfl_xor_sync(0xffffffffu, q, o);
    const float rs = rsqrtf(q * (1.0f / 256.0f) + 1e-5f);

    float4 w0 = *reinterpret_cast<const float4*>(lw + lane * 4);
    float4 w1 = *reinterpret_cast<const float4*>(lw + 128 + lane * 4);
    float4 c0 = *reinterpret_cast<const float4*>(lb + lane * 4);
    float4 c1 = *reinterpret_cast<const float4*>(lb + 128 + lane * 4);

    v0.x = (v0.x - mu) * rs * w0.x + c0.x;
    v0.y = (v0.y - mu) * rs * w0.y + c0.y;
    v0.z = (v0.z - mu) * rs * w0.z + c0.z;
    v0.w = (v0.w - mu) * rs * w0.w + c0.w;
    v1.x = (v1.x - mu) * rs * w1.x + c1.x;
    v1.y = (v1.y - mu) * rs * w1.y + c1.y;
    v1.z = (v1.z - mu) * rs * w1.z + c1.z;
    v1.w = (v1.w - mu) * rs * w1.w + c1.w;

    *reinterpret_cast<float4*>(p + lane * 4) = v0;
    *reinterpret_cast<float4*>(p + 128 + lane * 4) = v1;
}

// ---------------------------------------------------------------------------
extern "C" void kernel_launch(void* const* d_in, const int* in_sizes, int n_in,
                              void* d_out, int out_size)
{
    const float* x     = (const float*)d_in[0];
    const float* h0    = (const float*)d_in[1];
    const float* masks = (const float*)d_in[2];
    const float* W_ih  = (const float*)d_in[3];
    const float* W_hh  = (const float*)d_in[4];
    const float* b_ih  = (const float*)d_in[5];
    const float* b_hh  = (const float*)d_in[6];
    const float* ln_w  = (const float*)d_in[7];
    const float* ln_b  = (const float*)d_in[8];
    float* out = (float*)d_out;

    (void)in_sizes; (void)n_in; (void)out_size;

    cudaFuncSetAttribute(gi_mma, cudaFuncAttributeMaxDynamicSharedMemorySize, GI_SMEM);
    cudaFuncSetAttribute(gru_scan_mma, cudaFuncAttributeMaxDynamicSharedMemorySize, SMEM_SCAN);

    dim3 gA(G3 / 64, (T_STEPS * B_SZ) / 128);   // (12, 4096)
    gi_mma<<<gA, 256, GI_SMEM>>>(x, W_ih, b_ih);

    gru_scan_mma<<<SC_GRID, 512, SMEM_SCAN>>>(h0, masks, W_hh, b_hh, out);

    ln_kernel<<<(T_STEPS * B_SZ) / 8, 256>>>(out, ln_w, ln_b);
}

// round 7
// speedup vs baseline: 3.2277x; 1.1399x over previous
#include <cuda_runtime.h>
#include <cuda_bf16.h>
#include <cstdint>

#define T_STEPS 512
#define B_SZ    1024
#define D_IN    128
#define H_SZ    256
#define G3      (3 * H_SZ)   // 768

#define SC_GRID 128          // 16 b-tiles x 8 j-tiles, 1 CTA/SM, 512 thr

// ---------------------------------------------------------------------------
// Scratch (device globals)
// ---------------------------------------------------------------------------
__device__ float g_gi[(size_t)T_STEPS * B_SZ * G3];
// h exchange: per (ping, group) one 64x256 bf16 tile image, hi plane then lo
// plane, already in the swizzled smem layout (pure byte copy to stage).
__device__ __align__(16) unsigned char g_htile[2][16][2 * 32768];
// per-group producer flags: 8 CTAs x u32, one 32B segment per group
__device__ __align__(32) unsigned g_flags[16][8];

// ---------------------------------------------------------------------------
// Helpers
// ---------------------------------------------------------------------------
__device__ __forceinline__ unsigned smem_u32(const void* p) {
    unsigned a;
    asm("{ .reg .u64 t; cvta.to.shared.u64 t, %1; cvt.u32.u64 %0, t; }" : "=r"(a) : "l"(p));
    return a;
}

// 512 B/row tile (256 bf16), 16B-chunk XOR swizzle (scan tiles)
__device__ __forceinline__ unsigned toff(int row, int chunk) {
    return (unsigned)row * 512u + (unsigned)((chunk ^ (row & 7)) << 4);
}
// 256 B/row variant (gi tiles, K=128)
__device__ __forceinline__ unsigned toff128(int row, int chunk) {
    return (unsigned)row * 256u + (unsigned)((chunk ^ (row & 7)) << 4);
}

__device__ __forceinline__ uint4 pack8(const unsigned s[8]) {
    return make_uint4(s[0] | (s[1] << 16), s[2] | (s[3] << 16),
                      s[4] | (s[5] << 16), s[6] | (s[7] << 16));
}

__device__ __forceinline__ void split8(const float v[8], uint4& hi, uint4& lo) {
    unsigned h[8], l[8];
#pragma unroll
    for (int i = 0; i < 8; i++) {
        __nv_bfloat16 bh = __float2bfloat16(v[i]);
        float fh = __bfloat162float(bh);
        __nv_bfloat16 bl = __float2bfloat16(v[i] - fh);
        h[i] = (unsigned)__bfloat16_as_ushort(bh);
        l[i] = (unsigned)__bfloat16_as_ushort(bl);
    }
    hi = pack8(h); lo = pack8(l);
}

__device__ __forceinline__ void split4(const float v[4], uint2& hi, uint2& lo) {
    unsigned h[4], l[4];
#pragma unroll
    for (int i = 0; i < 4; i++) {
        __nv_bfloat16 bh = __float2bfloat16(v[i]);
        float fh = __bfloat162float(bh);
        __nv_bfloat16 bl = __float2bfloat16(v[i] - fh);
        h[i] = (unsigned)__bfloat16_as_ushort(bh);
        l[i] = (unsigned)__bfloat16_as_ushort(bl);
    }
    hi = make_uint2(h[0] | (h[1] << 16), h[2] | (h[3] << 16));
    lo = make_uint2(l[0] | (l[1] << 16), l[2] | (l[3] << 16));
}

__device__ __forceinline__ void unpack2(unsigned hi, unsigned lo, float& f0, float& f1) {
    f0 = __uint_as_float(hi << 16)         + __uint_as_float(lo << 16);
    f1 = __uint_as_float(hi & 0xffff0000u) + __uint_as_float(lo & 0xffff0000u);
}

__device__ __forceinline__ float fast_sigmoid(float x) {
    return __fdividef(1.0f, 1.0f + __expf(-x));
}
__device__ __forceinline__ float fast_tanh(float x) {
    return 1.0f - 2.0f * __fdividef(1.0f, __expf(2.0f * x) + 1.0f);
}

#define LDM4(r, a)                                                             \
    asm volatile("ldmatrix.sync.aligned.m8n8.x4.shared.b16 {%0,%1,%2,%3}, [%4];" \
        : "=r"((r)[0]), "=r"((r)[1]), "=r"((r)[2]), "=r"((r)[3]) : "r"(a))

#define MMA16816(c, a, b0v, b1v)                                               \
    asm volatile("mma.sync.aligned.m16n8k16.row.col.f32.bf16.bf16.f32 "        \
        "{%0,%1,%2,%3}, {%4,%5,%6,%7}, {%8,%9}, {%0,%1,%2,%3};"                \
        : "+f"((c)[0]), "+f"((c)[1]), "+f"((c)[2]), "+f"((c)[3])               \
        : "r"((a)[0]), "r"((a)[1]), "r"((a)[2]), "r"((a)[3]), "r"(b0v), "r"(b1v))

#define CP_ASYNC16(dst, src)                                                   \
    asm volatile("cp.async.cg.shared.global [%0], [%1], 16;" :: "r"(dst), "l"(src))

#define LDV4_VOL(r, p)                                                         \
    asm volatile("ld.volatile.global.v4.u32 {%0,%1,%2,%3}, [%4];"              \
        : "=r"((r).x), "=r"((r).y), "=r"((r).z), "=r"((r).w) : "l"(p))

// ---------------------------------------------------------------------------
// Kernel A: gi = x @ W_ih^T + b_ih  via bf16-split mma.sync (unchanged)
// ---------------------------------------------------------------------------
#define GI_SAHI 0u
#define GI_SALO 32768u
#define GI_SBHI 65536u
#define GI_SBLO 81920u
#define GI_SMEM 98304

__global__ void __launch_bounds__(256, 2)
gi_mma(const float* __restrict__ x,
       const float* __restrict__ W_ih,
       const float* __restrict__ b_ih)
{
    extern __shared__ char sm[];
    const unsigned sb = smem_u32(sm);

    const int tid = threadIdx.x;
    const size_t mbase = (size_t)blockIdx.y * 128;
    const int nbase = blockIdx.x * 64;

#pragma unroll
    for (int c = tid; c < 128 * 16; c += 256) {
        int r = c >> 4, ch = c & 15;
        const float* xp = x + (mbase + r) * D_IN + ch * 8;
        float v[8];
        *reinterpret_cast<float4*>(v)     = *reinterpret_cast<const float4*>(xp);
        *reinterpret_cast<float4*>(v + 4) = *reinterpret_cast<const float4*>(xp + 4);
        uint4 hi, lo; split8(v, hi, lo);
        unsigned off = toff128(r, ch);
        *reinterpret_cast<uint4*>(sm + GI_SAHI + off) = hi;
        *reinterpret_cast<uint4*>(sm + GI_SALO + off) = lo;
    }
#pragma unroll
    for (int c = tid; c < 64 * 16; c += 256) {
        int r = c >> 4, ch = c & 15;
        const float* wp = W_ih + (size_t)(nbase + r) * D_IN + ch * 8;
        float v[8];
        *reinterpret_cast<float4*>(v)     = *reinterpret_cast<const float4*>(wp);
        *reinterpret_cast<float4*>(v + 4) = *reinterpret_cast<const float4*>(wp + 4);
        uint4 hi, lo; split8(v, hi, lo);
        unsigned off = toff128(r, ch);
        *reinterpret_cast<uint4*>(sm + GI_SBHI + off) = hi;
        *reinterpret_cast<uint4*>(sm + GI_SBLO + off) = lo;
    }
    __syncthreads();

    const int lane = tid & 31;
    const int w = tid >> 5;
    const int wm = w & 3;
    const int wn = w >> 2;
    const int ra    = (lane & 7) + ((lane & 8) ? 8 : 0);
    const int parA  = (lane >> 4) & 1;
    const int rowA0 = wm * 32 + ra;
    const int rbrel = (lane & 7) + (((lane >> 4) & 1) ? 8 : 0);
    const int parB  = (lane >> 3) & 1;
    const int rowB0 = wn * 32 + rbrel;
    const int rowB1 = rowB0 + 16;

    float acc[2][4][4] = {};

#pragma unroll
    for (int ks = 0; ks < 8; ks++) {
        const int kc = ks * 2;
        unsigned ah0[4], ah1[4], al0[4], al1[4];
        {
            unsigned o0 = (unsigned)rowA0 * 256u + (unsigned)(((kc + parA) ^ (rowA0 & 7)) << 4);
            unsigned o1 = (unsigned)(rowA0 + 16) * 256u + (unsigned)(((kc + parA) ^ (rowA0 & 7)) << 4);
            LDM4(ah0, sb + GI_SAHI + o0);
            LDM4(ah1, sb + GI_SAHI + o1);
            LDM4(al0, sb + GI_SALO + o0);
            LDM4(al1, sb + GI_SALO + o1);
        }
        unsigned bh0[4], bh1[4], bl0[4], bl1[4];
        {
            unsigned o0 = (unsigned)rowB0 * 256u + (unsigned)(((kc + parB) ^ (rowB0 & 7)) << 4);
            unsigned o1 = (unsigned)rowB1 * 256u + (unsigned)(((kc + parB) ^ (rowB1 & 7)) << 4);
            LDM4(bh0, sb + GI_SBHI + o0);
            LDM4(bh1, sb + GI_SBHI + o1);
            LDM4(bl0, sb + GI_SBLO + o0);
            LDM4(bl1, sb + GI_SBLO + o1);
        }
        MMA16816(acc[0][0], ah0, bh0[0], bh0[1]); MMA16816(acc[0][1], ah0, bh0[2], bh0[3]);
        MMA16816(acc[0][2], ah0, bh1[0], bh1[1]); MMA16816(acc[0][3], ah0, bh1[2], bh1[3]);
        MMA16816(acc[1][0], ah1, bh0[0], bh0[1]); MMA16816(acc[1][1], ah1, bh0[2], bh0[3]);
        MMA16816(acc[1][2], ah1, bh1[0], bh1[1]); MMA16816(acc[1][3], ah1, bh1[2], bh1[3]);
        MMA16816(acc[0][0], ah0, bl0[0], bl0[1]); MMA16816(acc[0][1], ah0, bl0[2], bl0[3]);
        MMA16816(acc[0][2], ah0, bl1[0], bl1[1]); MMA16816(acc[0][3], ah0, bl1[2], bl1[3]);
        MMA16816(acc[1][0], ah1, bl0[0], bl0[1]); MMA16816(acc[1][1], ah1, bl0[2], bl0[3]);
        MMA16816(acc[1][2], ah1, bl1[0], bl1[1]); MMA16816(acc[1][3], ah1, bl1[2], bl1[3]);
        MMA16816(acc[0][0], al0, bh0[0], bh0[1]); MMA16816(acc[0][1], al0, bh0[2], bh0[3]);
        MMA16816(acc[0][2], al0, bh1[0], bh1[1]); MMA16816(acc[0][3], al0, bh1[2], bh1[3]);
        MMA16816(acc[1][0], al1, bh0[0], bh0[1]); MMA16816(acc[1][1], al1, bh0[2], bh0[3]);
        MMA16816(acc[1][2], al1, bh1[0], bh1[1]); MMA16816(acc[1][3], al1, bh1[2], bh1[3]);
    }

    const int tr = lane >> 2;
    const int tc = (lane & 3) * 2;
#pragma unroll
    for (int i = 0; i < 2; i++) {
#pragma unroll
        for (int jn = 0; jn < 4; jn++) {
            const int col = nbase + wn * 32 + (jn >> 1) * 16 + (jn & 1) * 8 + tc;
            float2 bias = *reinterpret_cast<const float2*>(b_ih + col);
            const size_t row0 = mbase + wm * 32 + i * 16 + tr;
            float2 v0 = make_float2(acc[i][jn][0] + bias.x, acc[i][jn][1] + bias.y);
            float2 v1 = make_float2(acc[i][jn][2] + bias.x, acc[i][jn][3] + bias.y);
            *reinterpret_cast<float2*>(g_gi + row0 * G3 + col)       = v0;
            *reinterpret_cast<float2*>(g_gi + (row0 + 8) * G3 + col) = v1;
        }
    }
}

// ---------------------------------------------------------------------------
// Persistent GRU scan + fused LayerNorm.
// smem: bias 512 | gh0 26624 | gh1 26624 | A_hi 32768 | A_lo 32768 |
//       W_hi 49152 | W_lo 49152 | lnw 1024 | lnb 1024  => 219648 B
// ---------------------------------------------------------------------------
#define S_BIAS 0u
#define S_GH0  512u
#define S_GH1  27136u
#define S_AHI  53760u
#define S_ALO  86528u
#define S_WHI  119296u
#define S_WLO  168448u
#define S_LNW  217600u
#define S_LNB  218624u
#define SMEM_SCAN 219648
#define GH_STR 104
#define GH_HALF 6656   // floats between gh0 and gh1

__global__ void __launch_bounds__(512, 1)
gru_scan_mma(const float* __restrict__ h0,
             const float* __restrict__ masks,
             const float* __restrict__ W_hh,
             const float* __restrict__ b_hh,
             const float* __restrict__ ln_w,
             const float* __restrict__ ln_b,
             float* __restrict__ out)
{
    extern __shared__ char smem[];
    const unsigned sbase = smem_u32(smem);
    float* sbias = reinterpret_cast<float*>(smem + S_BIAS);
    float* sgh   = reinterpret_cast<float*>(smem + S_GH0);
    float* slnw  = reinterpret_cast<float*>(smem + S_LNW);
    float* slnb  = reinterpret_cast<float*>(smem + S_LNB);

    const int tid = threadIdx.x;
    const int bi = blockIdx.x >> 3;   // group 0..15
    const int ji = blockIdx.x & 7;
    const int b0 = bi * 64;
    const int j0 = ji * 32;

    // base snapshot of the flag protocol (all 8 group flags equal here)
    unsigned bar_base;
    {
        const unsigned* fp = &g_flags[bi][ji];
        asm volatile("ld.volatile.global.u32 %0, [%1];" : "=r"(bar_base) : "l"(fp));
    }

    // ---- stage W_hh slice split to bf16 ----
    for (int c = tid; c < 96 * 32; c += 512) {
        int r  = c >> 5;
        int ch = c & 31;
        int grow = (r >> 5) * H_SZ + j0 + (r & 31);
        float v[8];
        *reinterpret_cast<float4*>(v)     = *reinterpret_cast<const float4*>(W_hh + (size_t)grow * H_SZ + ch * 8);
        *reinterpret_cast<float4*>(v + 4) = *reinterpret_cast<const float4*>(W_hh + (size_t)grow * H_SZ + ch * 8 + 4);
        uint4 hi, lo;
        split8(v, hi, lo);
        unsigned off = toff(r, ch);
        *reinterpret_cast<uint4*>(smem + S_WHI + off) = hi;
        *reinterpret_cast<uint4*>(smem + S_WLO + off) = lo;
    }
    if (tid < 96) sbias[tid] = b_hh[(tid >> 5) * H_SZ + j0 + (tid & 31)];
    if (tid < 256) { slnw[tid] = ln_w[tid]; slnb[tid] = ln_b[tid]; }

    // ---- MMA mapping (16 warps: 4 m x 2 n x 2 k-half) ----
    const int lane = tid & 31;
    const int w = tid >> 5;
    const int wm = w & 3;
    const int wn = (w >> 2) & 1;
    const int kh = w >> 3;
    const int rowA = wm * 16 + (lane & 7) + ((lane & 8) ? 8 : 0);
    const int parA = (lane >> 4) & 1;
    const int rbrel = (lane & 7) + (((lane >> 4) & 1) ? 8 : 0);
    const int parB = (lane >> 3) & 1;
    int rowB[3];
#pragma unroll
    for (int p = 0; p < 3; p++) rowB[p] = wn * 48 + p * 16 + rbrel;
    float* sghk = sgh + kh * GH_HALF;

    // ---- gate mapping: thread handles (row gr, 4 j) ----
    const int gr = tid >> 3;
    const int gq = tid & 7;
    const int jj0 = gq * 4;
    const int b = b0 + gr;
    const int jg = j0 + jj0;
    const unsigned hpo = toff(gr, jg >> 3) + (unsigned)((jg & 7) << 1);

    // ---- fused-LN mapping: warps 0-7 each own one of this CTA's 8 rows ----
    const int lrow = ji * 8 + w;                // local row in the 64-row tile
    const unsigned lnoff = toff(lrow, lane);    // lane = 16B chunk = 8 cols
    float lnw8[8], lnb8[8];

    __syncthreads();
    if (w < 8) {
        *reinterpret_cast<float4*>(lnw8)     = *reinterpret_cast<const float4*>(&slnw[lane * 8]);
        *reinterpret_cast<float4*>(lnw8 + 4) = *reinterpret_cast<const float4*>(&slnw[lane * 8 + 4]);
        *reinterpret_cast<float4*>(lnb8)     = *reinterpret_cast<const float4*>(&slnb[lane * 8]);
        *reinterpret_cast<float4*>(lnb8 + 4) = *reinterpret_cast<const float4*>(&slnb[lane * 8 + 4]);
    }

    for (int t = 0; t < T_STEPS; t++) {
        // ---- stage h tile (unmasked, pre-split, pre-swizzled) ----
        if (t == 0) {
            for (int c = tid; c < 64 * 32; c += 512) {
                int r = c >> 5, ch = c & 31;
                const float* hp = h0 + (size_t)(b0 + r) * H_SZ + ch * 8;
                float v[8];
                *reinterpret_cast<float4*>(v)     = *reinterpret_cast<const float4*>(hp);
                *reinterpret_cast<float4*>(v + 4) = *reinterpret_cast<const float4*>(hp + 4);
                uint4 hi, lo;
                split8(v, hi, lo);
                unsigned off = toff(r, ch);
                *reinterpret_cast<uint4*>(smem + S_AHI + off) = hi;
                *reinterpret_cast<uint4*>(smem + S_ALO + off) = lo;
            }
        } else {
            const unsigned char* src = g_htile[(t - 1) & 1][bi];
#pragma unroll
            for (int c = tid; c < 4096; c += 512) {
                CP_ASYNC16(sbase + S_AHI + (unsigned)c * 16u, src + (size_t)c * 16);
            }
            asm volatile("cp.async.commit_group;");
        }

        // ---- gi + mask prefetch ----
        float gir[4], giz[4], gin[4];
        {
            const float* gib = g_gi + ((size_t)t * B_SZ + b) * G3 + jg;
            *reinterpret_cast<float4*>(gir) = __ldcs(reinterpret_cast<const float4*>(gib));
            *reinterpret_cast<float4*>(giz) = __ldcs(reinterpret_cast<const float4*>(gib + H_SZ));
            *reinterpret_cast<float4*>(gin) = __ldcs(reinterpret_cast<const float4*>(gib + 2 * H_SZ));
        }
        const float m = __ldg(masks + (size_t)t * B_SZ + b);

        if (t != 0) {
            asm volatile("cp.async.wait_group 0;" ::: "memory");
        }
        __syncthreads();

        // ---- tensor GEMM: this warp does 8 k-steps of its k-half ----
        float acc[6][4] = {};
#pragma unroll
        for (int ks = 0; ks < 8; ks++) {
            const int kc = (kh * 8 + ks) * 2;
            unsigned ahi[4], alo[4];
            unsigned aoffs = (unsigned)rowA * 512u + (unsigned)(((kc + parA) ^ (rowA & 7)) << 4);
            LDM4(ahi, sbase + S_AHI + aoffs);
            LDM4(alo, sbase + S_ALO + aoffs);
#pragma unroll
            for (int p = 0; p < 3; p++) {
                unsigned boffs = (unsigned)rowB[p] * 512u + (unsigned)(((kc + parB) ^ (rowB[p] & 7)) << 4);
                unsigned bh[4], bl[4];
                LDM4(bh, sbase + S_WHI + boffs);
                LDM4(bl, sbase + S_WLO + boffs);
                MMA16816(acc[2 * p],     ahi, bh[0], bh[1]);
                MMA16816(acc[2 * p + 1], ahi, bh[2], bh[3]);
                MMA16816(acc[2 * p],     ahi, bl[0], bl[1]);
                MMA16816(acc[2 * p + 1], ahi, bl[2], bl[3]);
                MMA16816(acc[2 * p],     alo, bh[0], bh[1]);
                MMA16816(acc[2 * p + 1], alo, bh[2], bh[3]);
            }
        }

        // ---- accumulators -> smem partials ----
        {
            const int r0 = wm * 16 + lane / 4;
            const int cb = wn * 48 + (lane % 4) * 2;
#pragma unroll
            for (int i = 0; i < 6; i++) {
                const int col = cb + (i >> 1) * 16 + (i & 1) * 8;
                *reinterpret_cast<float2*>(&sghk[r0 * GH_STR + col])       = make_float2(acc[i][0], acc[i][1]);
                *reinterpret_cast<float2*>(&sghk[(r0 + 8) * GH_STR + col]) = make_float2(acc[i][2], acc[i][3]);
            }
        }
        __syncthreads();

        // ---- gates (mask folded) + h exchange write ----
        {
            float4 r0 = *reinterpret_cast<const float4*>(&sgh[gr * GH_STR + jj0]);
            float4 r1 = *reinterpret_cast<const float4*>(&sgh[GH_HALF + gr * GH_STR + jj0]);
            float4 z0 = *reinterpret_cast<const float4*>(&sgh[gr * GH_STR + 32 + jj0]);
            float4 z1 = *reinterpret_cast<const float4*>(&sgh[GH_HALF + gr * GH_STR + 32 + jj0]);
            float4 n0 = *reinterpret_cast<const float4*>(&sgh[gr * GH_STR + 64 + jj0]);
            float4 n1 = *reinterpret_cast<const float4*>(&sgh[GH_HALF + gr * GH_STR + 64 + jj0]);
            float ghr[4] = {r0.x + r1.x, r0.y + r1.y, r0.z + r1.z, r0.w + r1.w};
            float ghz[4] = {z0.x + z1.x, z0.y + z1.y, z0.z + z1.z, z0.w + z1.w};
            float ghn[4] = {n0.x + n1.x, n0.y + n1.y, n0.z + n1.z, n0.w + n1.w};

            float hpv[4];
            {
                uint2 hi = *reinterpret_cast<const uint2*>(smem + S_AHI + hpo);
                uint2 lo = *reinterpret_cast<const uint2*>(smem + S_ALO + hpo);
                unpack2(hi.x, lo.x, hpv[0], hpv[1]);
                unpack2(hi.y, lo.y, hpv[2], hpv[3]);
            }

            float hv[4];
#pragma unroll
            for (int i = 0; i < 4; i++) {
                float br = sbias[jj0 + i];
                float bz = sbias[32 + jj0 + i];
                float bn = sbias[64 + jj0 + i];
                float r = fast_sigmoid(gir[i] + m * ghr[i] + br);
                float z = fast_sigmoid(giz[i] + m * ghz[i] + bz);
                float n = fast_tanh(gin[i] + r * (m * ghn[i] + bn));
                hv[i] = (1.0f - z) * n + z * (m * hpv[i]);
            }

            // h exchange write: split, already-swizzled tile image
            uint2 oh, ol;
            split4(hv, oh, ol);
            unsigned char* dst = g_htile[t & 1][bi];
            *reinterpret_cast<uint2*>(dst + hpo)         = oh;
            *reinterpret_cast<uint2*>(dst + 32768 + hpo) = ol;

            if (t == T_STEPS - 1) {
                float* fp = out + (size_t)T_STEPS * B_SZ * H_SZ + (size_t)b * H_SZ + jg;
                *reinterpret_cast<float4*>(fp) = make_float4(hv[0], hv[1], hv[2], hv[3]);
            }
        }

        // ---- release this CTA's flag as soon as h writes are visible ----
        __syncthreads();
        const unsigned target = bar_base + (unsigned)t + 1u;
        if (tid == 0) {
            asm volatile("st.release.gpu.global.u32 [%0], %1;"
                         :: "l"(&g_flags[bi][ji]), "r"(target) : "memory");
        }

        // ---- fused LN of y(t-1) = A tile rows (hides peer skew) ----
        if (t > 0 && w < 8) {
            uint4 hi = *reinterpret_cast<const uint4*>(smem + S_AHI + lnoff);
            uint4 lo = *reinterpret_cast<const uint4*>(smem + S_ALO + lnoff);
            float v[8];
            unpack2(hi.x, lo.x, v[0], v[1]);
            unpack2(hi.y, lo.y, v[2], v[3]);
            unpack2(hi.z, lo.z, v[4], v[5]);
            unpack2(hi.w, lo.w, v[6], v[7]);
            float s = v[0] + v[1] + v[2] + v[3] + v[4] + v[5] + v[6] + v[7];
#pragma unroll
            for (int o = 16; o; o >>= 1) s += __shfl_xor_sync(0xffffffffu, s, o);
            const float mu = s * (1.0f / 256.0f);
            float q = 0.f;
#pragma unroll
            for (int i = 0; i < 8; i++) { float d = v[i] - mu; q += d * d; }
#pragma unroll
            for (int o = 16; o; o >>= 1) q += __shfl_xor_sync(0xffffffffu, q, o);
            const float rs = rsqrtf(q * (1.0f / 256.0f) + 1e-5f);
            float o8[8];
#pragma unroll
            for (int i = 0; i < 8; i++) o8[i] = (v[i] - mu) * rs * lnw8[i] + lnb8[i];
            float* yp = out + ((size_t)(t - 1) * B_SZ + b0 + lrow) * H_SZ + lane * 8;
            *reinterpret_cast<float4*>(yp)     = *reinterpret_cast<float4*>(o8);
            *reinterpret_cast<float4*>(yp + 4) = *reinterpret_cast<float4*>(o8 + 4);
        }

        // ---- poll all 8 group flags ----
        if (tid == 0) {
            const unsigned* fb = &g_flags[bi][0];
            uint4 f0, f1;
            for (;;) {
                LDV4_VOL(f0, fb);
                LDV4_VOL(f1, fb + 4);
                if (f0.x == target && f0.y == target && f0.z == target && f0.w == target &&
                    f1.x == target && f1.y == target && f1.z == target && f1.w == target)
                    break;
            }
            asm volatile("fence.acq_rel.gpu;" ::: "memory");
        }
        __syncthreads();
    }

    // ---- epilogue: LN of y(T-1) from the final h tile ----
    {
        const unsigned char* src = g_htile[(T_STEPS - 1) & 1][bi];
#pragma unroll
        for (int c = tid; c < 4096; c += 512) {
            CP_ASYNC16(sbase + S_AHI + (unsigned)c * 16u, src + (size_t)c * 16);
        }
        asm volatile("cp.async.commit_group;");
        asm volatile("cp.async.wait_group 0;" ::: "memory");
        __syncthreads();

        if (w < 8) {
            uint4 hi = *reinterpret_cast<const uint4*>(smem + S_AHI + lnoff);
            uint4 lo = *reinterpret_cast<const uint4*>(smem + S_ALO + lnoff);
            float v[8];
            unpack2(hi.x, lo.x, v[0], v[1]);
            unpack2(hi.y, lo.y, v[2], v[3]);
            unpack2(hi.z, lo.z, v[4], v[5]);
            unpack2(hi.w, lo.w, v[6], v[7]);
            float s = v[0] + v[1] + v[2] + v[3] + v[4] + v[5] + v[6] + v[7];
#pragma unroll
            for (int o = 16; o; o >>= 1) s += __shfl_xor_sync(0xffffffffu, s, o);
            const float mu = s * (1.0f / 256.0f);
            float q = 0.f;
#pragma unroll
            for (int i = 0; i < 8; i++) { float d = v[i] - mu; q += d * d; }
#pragma unroll
            for (int o = 16; o; o >>= 1) q += __shfl_xor_sync(0xffffffffu, q, o);
            const float rs = rsqrtf(q * (1.0f / 256.0f) + 1e-5f);
            float o8[8];
#pragma unroll
            for (int i = 0; i < 8; i++) o8[i] = (v[i] - mu) * rs * lnw8[i] + lnb8[i];
            float* yp = out + ((size_t)(T_STEPS - 1) * B_SZ + b0 + lrow) * H_SZ + lane * 8;
            *reinterpret_cast<float4*>(yp)     = *reinterpret_cast<float4*>(o8);
            *reinterpret_cast<float4*>(yp + 4) = *reinterpret_cast<float4*>(o8 + 4);
        }
    }
}

// ---------------------------------------------------------------------------
extern "C" void kernel_launch(void* const* d_in, const int* in_sizes, int n_in,
                              void* d_out, int out_size)
{
    const float* x     = (const float*)d_in[0];
    const float* h0    = (const float*)d_in[1];
    const float* masks = (const float*)d_in[2];
    const float* W_ih  = (const float*)d_in[3];
    const float* W_hh  = (const float*)d_in[4];
    const float* b_ih  = (const float*)d_in[5];
    const float* b_hh  = (const float*)d_in[6];
    const float* ln_w  = (const float*)d_in[7];
    const float* ln_b  = (const float*)d_in[8];
    float* out = (float*)d_out;

    (void)in_sizes; (void)n_in; (void)out_size;

    cudaFuncSetAttribute(gi_mma, cudaFuncAttributeMaxDynamicSharedMemorySize, GI_SMEM);
    cudaFuncSetAttribute(gru_scan_mma, cudaFuncAttributeMaxDynamicSharedMemorySize, SMEM_SCAN);

    dim3 gA(G3 / 64, (T_STEPS * B_SZ) / 128);   // (12, 4096)
    gi_mma<<<gA, 256, GI_SMEM>>>(x, W_ih, b_ih);

    gru_scan_mma<<<SC_GRID, 512, SMEM_SCAN>>>(h0, masks, W_hh, b_hh, ln_w, ln_b, out);
}